// round 1
// baseline (speedup 1.0000x reference)
#include <cuda_runtime.h>
#include <math.h>

// Problem constants
constexpr int Bq  = 2;
constexpr int Sq  = 2048;
constexpr int Dq  = 1024;
constexpr int Hq  = 16;
constexpr int HDq = 64;
constexpr float NEGB = -10000.0f;

// ---------------------------------------------------------------------------
// Scratch (device globals: no allocation allowed)
// ---------------------------------------------------------------------------
__device__ __align__(16) float g_Q[Bq * Sq * Dq];   // projected Q, (B,S,D) layout (head-major inside D)
__device__ __align__(16) float g_K[Bq * Sq * Dq];
__device__ __align__(16) float g_V[Bq * Sq * Dq];
__device__ __align__(16) float g_C[Bq * Sq * Dq];   // attention context

// ---------------------------------------------------------------------------
// SGEMM: C[M,N] = A[M,K] @ W[N,K]^T   (all row-major, M,N multiples of 128, K mult of 8)
// 128x128x8 tile, 256 threads, 8x8 per thread (split 4+4 register layout for
// conflict-free LDS.128 on both operands).
// ---------------------------------------------------------------------------
constexpr int GBM = 128, GBN = 128, GBK = 8;

__global__ __launch_bounds__(256) void sgemm_abT(
    const float* __restrict__ A, const float* __restrict__ W,
    float* __restrict__ C, int M, int N, int K)
{
    __shared__ float As[GBK][GBM];
    __shared__ float Bs[GBK][GBN];

    const int tid = threadIdx.x;
    const int tx  = tid & 15;          // 0..15 -> N direction
    const int ty  = tid >> 4;          // 0..15 -> M direction
    const int m0  = blockIdx.y * GBM;
    const int n0  = blockIdx.x * GBN;

    // loader mapping: 1024 floats per tile = 256 float4, one per thread.
    const int ar = tid >> 1;           // tile row 0..127
    const int ac = (tid & 1) * 4;      // tile col 0 or 4

    float acc[8][8];
#pragma unroll
    for (int i = 0; i < 8; i++)
#pragma unroll
        for (int j = 0; j < 8; j++) acc[i][j] = 0.0f;

    const float* Arow = A + (size_t)(m0 + ar) * K + ac;
    const float* Wrow = W + (size_t)(n0 + ar) * K + ac;

    for (int k0 = 0; k0 < K; k0 += GBK) {
        float4 av = *(const float4*)(Arow + k0);
        float4 bv = *(const float4*)(Wrow + k0);
        As[ac + 0][ar] = av.x; As[ac + 1][ar] = av.y;
        As[ac + 2][ar] = av.z; As[ac + 3][ar] = av.w;
        Bs[ac + 0][ar] = bv.x; Bs[ac + 1][ar] = bv.y;
        Bs[ac + 2][ar] = bv.z; Bs[ac + 3][ar] = bv.w;
        __syncthreads();

#pragma unroll
        for (int kk = 0; kk < GBK; kk++) {
            float4 a0 = *(const float4*)&As[kk][ty * 4];
            float4 a1 = *(const float4*)&As[kk][64 + ty * 4];
            float4 b0 = *(const float4*)&Bs[kk][tx * 4];
            float4 b1 = *(const float4*)&Bs[kk][64 + tx * 4];
            float a[8] = {a0.x, a0.y, a0.z, a0.w, a1.x, a1.y, a1.z, a1.w};
            float bb[8] = {b0.x, b0.y, b0.z, b0.w, b1.x, b1.y, b1.z, b1.w};
#pragma unroll
            for (int i = 0; i < 8; i++)
#pragma unroll
                for (int j = 0; j < 8; j++)
                    acc[i][j] = fmaf(a[i], bb[j], acc[i][j]);
        }
        __syncthreads();
    }

#pragma unroll
    for (int i = 0; i < 8; i++) {
        int r = m0 + ((i < 4) ? (ty * 4 + i) : (64 + ty * 4 + i - 4));
        float4 c0 = make_float4(acc[i][0], acc[i][1], acc[i][2], acc[i][3]);
        float4 c1 = make_float4(acc[i][4], acc[i][5], acc[i][6], acc[i][7]);
        *(float4*)&C[(size_t)r * N + n0 + tx * 4]      = c0;
        *(float4*)&C[(size_t)r * N + n0 + 64 + tx * 4] = c1;
    }
}

// ---------------------------------------------------------------------------
// Flash attention: 64x64 tiles, online softmax. Works on g_Q/g_K/g_V in
// (B,S,D) layout with head offset h*HD. Masked scores -> -1e30 (exactly
// matches fp32 reference for any row with >=1 valid column, since
// exp(-10000 - m) underflows to 0 there). Degenerate rows fixed by cleanup.
// ---------------------------------------------------------------------------
constexpr int FM = 64, FN = 64, FP = HDq + 4;  // padded pitch (68) keeps 16B align

__global__ __launch_bounds__(256) void flash_kernel(
    const float* __restrict__ Qg, const float* __restrict__ Kg,
    const float* __restrict__ Vg, const int* __restrict__ amask,
    const int* __restrict__ mfp, float* __restrict__ Ctx)
{
    extern __shared__ float smf[];
    float* Qs = smf;                 // [64][68]
    float* Ks = Qs + FM * FP;        // [64][68]
    float* Vs = Ks + FN * FP;        // [64][68]
    float* Ps = Vs + FN * FP;        // [64][68]
    int*   ms = (int*)(Ps + FM * FP);

    const int tid = threadIdx.x;
    const int tx = tid & 15, ty = tid >> 4;
    const int bh = blockIdx.y;
    const int b = bh >> 4, h = bh & 15;
    const int q0 = blockIdx.x * FM;
    const int causal = *mfp;
    const float scale = 0.125f;      // 1/sqrt(64)

    // Load Q tile (64 rows x 64 cols) as float4
    const float* Qbase = Qg + ((size_t)b * Sq + q0) * Dq + h * HDq;
    for (int idx = tid; idx < 64 * 16; idx += 256) {
        int r = idx >> 4, c4 = (idx & 15) << 2;
        *(float4*)&Qs[r * FP + c4] = *(const float4*)&Qbase[(size_t)r * Dq + c4];
    }

    float Ot[4][4];
    float mrow[4], lrow[4];
#pragma unroll
    for (int i = 0; i < 4; i++) {
        mrow[i] = -1e30f; lrow[i] = 0.0f;
#pragma unroll
        for (int j = 0; j < 4; j++) Ot[i][j] = 0.0f;
    }

    const int tEnd = causal ? (blockIdx.x + 1) : (Sq / FN);

    for (int t = 0; t < tEnd; t++) {
        const int j0 = t * FN;
        const float* Kbase = Kg + ((size_t)b * Sq + j0) * Dq + h * HDq;
        const float* Vbase = Vg + ((size_t)b * Sq + j0) * Dq + h * HDq;
        for (int idx = tid; idx < 64 * 16; idx += 256) {
            int r = idx >> 4, c4 = (idx & 15) << 2;
            *(float4*)&Ks[r * FP + c4] = *(const float4*)&Kbase[(size_t)r * Dq + c4];
            *(float4*)&Vs[r * FP + c4] = *(const float4*)&Vbase[(size_t)r * Dq + c4];
        }
        if (tid < FN) ms[tid] = amask[b * Sq + j0 + tid];
        __syncthreads();

        // ---- S = Q K^T (4x4 per thread) ----
        float s[4][4];
#pragma unroll
        for (int i = 0; i < 4; i++)
#pragma unroll
            for (int j = 0; j < 4; j++) s[i][j] = 0.0f;

#pragma unroll
        for (int d = 0; d < HDq; d += 4) {
            float4 qa[4], kb[4];
#pragma unroll
            for (int i = 0; i < 4; i++) qa[i] = *(const float4*)&Qs[(ty * 4 + i) * FP + d];
#pragma unroll
            for (int j = 0; j < 4; j++) kb[j] = *(const float4*)&Ks[(tx * 4 + j) * FP + d];
#pragma unroll
            for (int i = 0; i < 4; i++)
#pragma unroll
                for (int j = 0; j < 4; j++) {
                    s[i][j] = fmaf(qa[i].x, kb[j].x, s[i][j]);
                    s[i][j] = fmaf(qa[i].y, kb[j].y, s[i][j]);
                    s[i][j] = fmaf(qa[i].z, kb[j].z, s[i][j]);
                    s[i][j] = fmaf(qa[i].w, kb[j].w, s[i][j]);
                }
        }

        // ---- masking + online softmax ----
#pragma unroll
        for (int i = 0; i < 4; i++) {
            const int rg = q0 + ty * 4 + i;
            float rmax = -1e30f;
#pragma unroll
            for (int j = 0; j < 4; j++) {
                const int jg = j0 + tx * 4 + j;
                const bool dead = (ms[tx * 4 + j] == 0) || (causal && jg > rg);
                float sv = dead ? -1e30f : s[i][j] * scale;
                s[i][j] = sv;
                rmax = fmaxf(rmax, sv);
            }
#pragma unroll
            for (int o = 8; o >= 1; o >>= 1)
                rmax = fmaxf(rmax, __shfl_xor_sync(0xffffffffu, rmax, o));

            const float mo = mrow[i];
            const float mn = fmaxf(mo, rmax);
            const float alpha = __expf(mo - mn);
            float rsum = 0.0f;
#pragma unroll
            for (int j = 0; j < 4; j++) {
                float p = (s[i][j] <= -1e29f) ? 0.0f : __expf(s[i][j] - mn);
                s[i][j] = p;
                rsum += p;
            }
#pragma unroll
            for (int o = 8; o >= 1; o >>= 1)
                rsum += __shfl_xor_sync(0xffffffffu, rsum, o);

            lrow[i] = lrow[i] * alpha + rsum;
            mrow[i] = mn;
#pragma unroll
            for (int d = 0; d < 4; d++) Ot[i][d] *= alpha;

            *(float4*)&Ps[(ty * 4 + i) * FP + tx * 4] =
                make_float4(s[i][0], s[i][1], s[i][2], s[i][3]);
        }
        __syncthreads();

        // ---- O += P V ----
#pragma unroll 8
        for (int j = 0; j < FN; j++) {
            float4 vv = *(const float4*)&Vs[j * FP + tx * 4];
            float pv0 = Ps[(ty * 4 + 0) * FP + j];
            float pv1 = Ps[(ty * 4 + 1) * FP + j];
            float pv2 = Ps[(ty * 4 + 2) * FP + j];
            float pv3 = Ps[(ty * 4 + 3) * FP + j];
            Ot[0][0] = fmaf(pv0, vv.x, Ot[0][0]); Ot[0][1] = fmaf(pv0, vv.y, Ot[0][1]);
            Ot[0][2] = fmaf(pv0, vv.z, Ot[0][2]); Ot[0][3] = fmaf(pv0, vv.w, Ot[0][3]);
            Ot[1][0] = fmaf(pv1, vv.x, Ot[1][0]); Ot[1][1] = fmaf(pv1, vv.y, Ot[1][1]);
            Ot[1][2] = fmaf(pv1, vv.z, Ot[1][2]); Ot[1][3] = fmaf(pv1, vv.w, Ot[1][3]);
            Ot[2][0] = fmaf(pv2, vv.x, Ot[2][0]); Ot[2][1] = fmaf(pv2, vv.y, Ot[2][1]);
            Ot[2][2] = fmaf(pv2, vv.z, Ot[2][2]); Ot[2][3] = fmaf(pv2, vv.w, Ot[2][3]);
            Ot[3][0] = fmaf(pv3, vv.x, Ot[3][0]); Ot[3][1] = fmaf(pv3, vv.y, Ot[3][1]);
            Ot[3][2] = fmaf(pv3, vv.z, Ot[3][2]); Ot[3][3] = fmaf(pv3, vv.w, Ot[3][3]);
        }
        __syncthreads();
    }

    // ---- epilogue: normalize and store ----
#pragma unroll
    for (int i = 0; i < 4; i++) {
        const float inv = (lrow[i] > 0.0f) ? (1.0f / lrow[i]) : 0.0f;
        const int rg = q0 + ty * 4 + i;
        float4 o4 = make_float4(Ot[i][0] * inv, Ot[i][1] * inv,
                                Ot[i][2] * inv, Ot[i][3] * inv);
        *(float4*)&Ctx[((size_t)b * Sq + rg) * Dq + h * HDq + tx * 4] = o4;
    }
}

// ---------------------------------------------------------------------------
// Exact cleanup for degenerate rows (causal prefix fully padded): reference
// semantics use NEG=-1e4 biases, so such rows attend to FUTURE tokens.
// Recompute the full-row softmax with exact NEG arithmetic and overwrite ctx.
// One block per (b,h); typically 0-3 rows per batch.
// ---------------------------------------------------------------------------
__global__ __launch_bounds__(256) void fix_degenerate(
    const float* __restrict__ Qg, const float* __restrict__ Kg,
    const float* __restrict__ Vg, const int* __restrict__ amask,
    const int* __restrict__ mfp, float* __restrict__ Ctx)
{
    const int b = blockIdx.x >> 4, h = blockIdx.x & 15;
    const int tid = threadIdx.x;
    const int causal = *mfp;

    __shared__ int   redi[256];
    __shared__ float redf[256];
    __shared__ float qrow[HDq];
    __shared__ float sc[Sq];

    // first valid position s0 in this batch's mask
    int local = Sq;
    for (int s = tid; s < Sq; s += 256)
        if (amask[b * Sq + s]) local = min(local, s);
    redi[tid] = local;
    __syncthreads();
    for (int o = 128; o > 0; o >>= 1) {
        if (tid < o) redi[tid] = min(redi[tid], redi[tid + o]);
        __syncthreads();
    }
    const int s0 = redi[0];
    int nrows;
    if (causal) nrows = s0;                 // rows 0..s0-1 have all-padded prefix
    else        nrows = (s0 == Sq) ? Sq : 0; // non-causal: degenerate only if fully padded
    if (nrows == 0) return;

    for (int i = 0; i < nrows; i++) {
        if (tid < HDq) qrow[tid] = Qg[((size_t)b * Sq + i) * Dq + h * HDq + tid];
        __syncthreads();

        // scores with exact NEG semantics
        for (int j = tid; j < Sq; j += 256) {
            const float* kr = Kg + ((size_t)b * Sq + j) * Dq + h * HDq;
            float acc = 0.0f;
#pragma unroll
            for (int d = 0; d < HDq; d++) acc = fmaf(qrow[d], kr[d], acc);
            float v = acc * 0.125f;
            if (causal && j > i) v += NEGB;
            if (amask[b * Sq + j] == 0) v = NEGB;
            sc[j] = v;
        }
        __syncthreads();

        // row max
        float lm = -1e30f;
        for (int j = tid; j < Sq; j += 256) lm = fmaxf(lm, sc[j]);
        redf[tid] = lm; __syncthreads();
        for (int o = 128; o > 0; o >>= 1) {
            if (tid < o) redf[tid] = fmaxf(redf[tid], redf[tid + o]);
            __syncthreads();
        }
        const float m = redf[0];
        __syncthreads();

        // exp + sum
        float ls = 0.0f;
        for (int j = tid; j < Sq; j += 256) {
            float p = __expf(sc[j] - m);
            sc[j] = p;
            ls += p;
        }
        redf[tid] = ls; __syncthreads();
        for (int o = 128; o > 0; o >>= 1) {
            if (tid < o) redf[tid] += redf[tid + o];
            __syncthreads();
        }
        const float l = redf[0];
        __syncthreads();

        // ctx row
        if (tid < HDq) {
            float acc = 0.0f;
            for (int j = 0; j < Sq; j++)
                acc = fmaf(sc[j], __ldg(&Vg[((size_t)b * Sq + j) * Dq + h * HDq + tid]), acc);
            Ctx[((size_t)b * Sq + i) * Dq + h * HDq + tid] = acc / l;
        }
        __syncthreads();
    }
}

// ---------------------------------------------------------------------------
// Launch
// ---------------------------------------------------------------------------
extern "C" void kernel_launch(void* const* d_in, const int* in_sizes, int n_in,
                              void* d_out, int out_size)
{
    const float* q     = (const float*)d_in[0];
    const float* k     = (const float*)d_in[1];
    const float* v     = (const float*)d_in[2];
    const int*   amask = (const int*)  d_in[3];
    const float* Wq    = (const float*)d_in[4];
    const float* Wk    = (const float*)d_in[5];
    const float* Wv    = (const float*)d_in[6];
    const float* Wo    = (const float*)d_in[7];
    const int*   mf    = (const int*)  d_in[8];
    float*       out   = (float*)d_out;

    float *gQ, *gK, *gV, *gC;
    cudaGetSymbolAddress((void**)&gQ, g_Q);
    cudaGetSymbolAddress((void**)&gK, g_K);
    cudaGetSymbolAddress((void**)&gV, g_V);
    cudaGetSymbolAddress((void**)&gC, g_C);

    const int M = Bq * Sq;           // 4096
    dim3 gg(Dq / GBN, M / GBM);      // (8, 32)
    sgemm_abT<<<gg, 256>>>(q, Wq, gQ, M, Dq, Dq);
    sgemm_abT<<<gg, 256>>>(k, Wk, gK, M, Dq, Dq);
    sgemm_abT<<<gg, 256>>>(v, Wv, gV, M, Dq, Dq);

    const size_t fsm = (size_t)(4 * FM * FP) * sizeof(float) + FN * sizeof(int);
    cudaFuncSetAttribute(flash_kernel, cudaFuncAttributeMaxDynamicSharedMemorySize, (int)fsm);
    flash_kernel<<<dim3(Sq / FM, Bq * Hq), 256, fsm>>>(gQ, gK, gV, amask, mf, gC);

    fix_degenerate<<<Bq * Hq, 256>>>(gQ, gK, gV, amask, mf, gC);

    sgemm_abT<<<gg, 256>>>(gC, Wo, out, M, Dq, Dq);
}

// round 3
// speedup vs baseline: 1.3469x; 1.3469x over previous
#include <cuda_runtime.h>
#include <math.h>
#include <stdint.h>

// Problem constants
constexpr int Bq  = 2;
constexpr int Sq  = 2048;
constexpr int Dq  = 1024;
constexpr int Hq  = 16;
constexpr int HDq = 64;
constexpr float NEGB = -10000.0f;

// ---------------------------------------------------------------------------
// Scratch (device globals: no allocation allowed)
// ---------------------------------------------------------------------------
__device__ __align__(16) float g_Q[Bq * Sq * Dq];
__device__ __align__(16) float g_K[Bq * Sq * Dq];
__device__ __align__(16) float g_V[Bq * Sq * Dq];
__device__ __align__(16) float g_C[Bq * Sq * Dq];

// ---------------------------------------------------------------------------
// Helpers
// ---------------------------------------------------------------------------
__device__ __forceinline__ uint32_t rtf32_bits(float x) {
    uint32_t u;
    asm("cvt.rna.tf32.f32 %0, %1;" : "=r"(u) : "f"(x));
    return u;
}

__device__ __forceinline__ void mma_tf32(
    float& c0, float& c1, float& c2, float& c3,
    uint32_t a0, uint32_t a1, uint32_t a2, uint32_t a3,
    uint32_t b0, uint32_t b1)
{
    asm volatile(
        "mma.sync.aligned.m16n8k8.row.col.f32.tf32.tf32.f32 "
        "{%0,%1,%2,%3}, {%4,%5,%6,%7}, {%8,%9}, {%0,%1,%2,%3};"
        : "+f"(c0), "+f"(c1), "+f"(c2), "+f"(c3)
        : "r"(a0), "r"(a1), "r"(a2), "r"(a3), "r"(b0), "r"(b1));
}

// ---------------------------------------------------------------------------
// tf32 mma.sync GEMM: C[M,N] = A[M,K] @ W[N,K]^T, fp32 accumulate.
// CTA tile 128x128, BK=32, 256 threads (8 warps, warp tile 64x32).
// Smem layout interleaves (k, k+4) pairs so every fragment load is one LDS.64:
//   pos(k) = (k & 24) + ((k & 3) << 1) + ((k & 4) >> 2)
// Row stride 40 floats -> conflict-free 64-bit LDS.
// Operands are rounded to tf32 (rna) in the loader.
// ---------------------------------------------------------------------------
constexpr int BM = 128, BN = 128, BK = 32;
constexpr int SSTR = 40;                         // smem row stride (floats)
constexpr int OPF  = BM * SSTR;                  // floats per operand buffer
constexpr uint32_t GEMM_SMEM = 2 * 2 * OPF * 4;  // 2 stages x (A+B) = 81920 B

__device__ __forceinline__ int kperm(int k) {
    return (k & 24) + ((k & 3) << 1) + ((k & 4) >> 2);
}

__global__ __launch_bounds__(256) void gemm_tf32(
    const float* __restrict__ A, const float* __restrict__ Wt,
    float* __restrict__ C, int M)
{
    extern __shared__ __align__(16) float sm[];
    // stage s: A at sm + s*2*OPF, B at sm + s*2*OPF + OPF

    const int tid  = threadIdx.x;
    const int lane = tid & 31;
    const int wid  = tid >> 5;
    const int g    = lane >> 2;        // 0..7
    const int t    = lane & 3;         // 0..3
    const int wm0  = (wid & 1) * 64;   // warp M offset
    const int wn0  = (wid >> 1) * 32;  // warp N offset
    const int m0   = blockIdx.y * BM;
    const int n0   = blockIdx.x * BN;

    // loader mapping: per operand 1024 float4 per chunk; 4 per thread
    const int c4  = tid & 7;           // float4 index within 32-float row
    const int r0  = tid >> 3;          // base row (0..31), rows r0 + 32*i
    const float* Ag = A  + (size_t)m0 * Dq + c4 * 4;
    const float* Bg = Wt + (size_t)n0 * Dq + c4 * 4;

    float cr[4][4][4];                 // [mt][nt][4]
#pragma unroll
    for (int i = 0; i < 4; i++)
#pragma unroll
        for (int j = 0; j < 4; j++)
#pragma unroll
            for (int e = 0; e < 4; e++) cr[i][j][e] = 0.0f;

    float4 apf[4], bpf[4];

    auto ldg_chunk = [&](int kc) {
#pragma unroll
        for (int i = 0; i < 4; i++) {
            apf[i] = *(const float4*)(Ag + (size_t)(r0 + 32 * i) * Dq + kc);
            bpf[i] = *(const float4*)(Bg + (size_t)(r0 + 32 * i) * Dq + kc);
        }
    };
    auto sts_chunk = [&](int s) {
        float* As = sm + s * 2 * OPF;
        float* Bs = As + OPF;
#pragma unroll
        for (int i = 0; i < 4; i++) {
            const int row = r0 + 32 * i;
            const float av[4] = {apf[i].x, apf[i].y, apf[i].z, apf[i].w};
            const float bv[4] = {bpf[i].x, bpf[i].y, bpf[i].z, bpf[i].w};
#pragma unroll
            for (int e = 0; e < 4; e++) {
                const int p = kperm(c4 * 4 + e);
                As[row * SSTR + p] = __uint_as_float(rtf32_bits(av[e]));
                Bs[row * SSTR + p] = __uint_as_float(rtf32_bits(bv[e]));
            }
        }
    };
    auto mma_chunk = [&](int s) {
        const float* As = sm + s * 2 * OPF;
        const float* Bs = As + OPF;
#pragma unroll
        for (int kk = 0; kk < BK; kk += 8) {
            uint32_t af[4][4];   // [mt][a0..a3]
            uint32_t bf[4][2];   // [nt][b0,b1]
#pragma unroll
            for (int mt = 0; mt < 4; mt++) {
                const int row = wm0 + mt * 16 + g;
                float2 lo = *(const float2*)&As[row * SSTR + kk + 2 * t];
                float2 hi = *(const float2*)&As[(row + 8) * SSTR + kk + 2 * t];
                af[mt][0] = __float_as_uint(lo.x);   // (g,   t)
                af[mt][2] = __float_as_uint(lo.y);   // (g,   t+4)
                af[mt][1] = __float_as_uint(hi.x);   // (g+8, t)
                af[mt][3] = __float_as_uint(hi.y);   // (g+8, t+4)
            }
#pragma unroll
            for (int nt = 0; nt < 4; nt++) {
                const int row = wn0 + nt * 8 + g;
                float2 bb = *(const float2*)&Bs[row * SSTR + kk + 2 * t];
                bf[nt][0] = __float_as_uint(bb.x);   // (k=t,   n=g)
                bf[nt][1] = __float_as_uint(bb.y);   // (k=t+4, n=g)
            }
#pragma unroll
            for (int mt = 0; mt < 4; mt++)
#pragma unroll
                for (int nt = 0; nt < 4; nt++)
                    mma_tf32(cr[mt][nt][0], cr[mt][nt][1],
                             cr[mt][nt][2], cr[mt][nt][3],
                             af[mt][0], af[mt][1], af[mt][2], af[mt][3],
                             bf[nt][0], bf[nt][1]);
        }
    };

    constexpr int NCH = Dq / BK;       // 32
    ldg_chunk(0);
    sts_chunk(0);
    __syncthreads();
    for (int c = 0; c < NCH; c++) {
        if (c + 1 < NCH) ldg_chunk((c + 1) * BK);
        mma_chunk(c & 1);
        __syncthreads();
        if (c + 1 < NCH) {
            sts_chunk((c + 1) & 1);
            __syncthreads();
        }
    }

    // epilogue: each thread owns C[g + {0,8}][2t, 2t+1] per 16x8 tile
#pragma unroll
    for (int mt = 0; mt < 4; mt++) {
#pragma unroll
        for (int nt = 0; nt < 4; nt++) {
            const int row = m0 + wm0 + mt * 16 + g;
            const int col = n0 + wn0 + nt * 8 + 2 * t;
            *(float2*)&C[(size_t)row * Dq + col] =
                make_float2(cr[mt][nt][0], cr[mt][nt][1]);
            *(float2*)&C[(size_t)(row + 8) * Dq + col] =
                make_float2(cr[mt][nt][2], cr[mt][nt][3]);
        }
    }
}

// ---------------------------------------------------------------------------
// Flash attention (fp32): 64x64 tiles, online softmax, causal tile skipping.
// ---------------------------------------------------------------------------
constexpr int FM = 64, FN = 64, FP = HDq + 4;

__global__ __launch_bounds__(256) void flash_kernel(
    const float* __restrict__ Qg, const float* __restrict__ Kg,
    const float* __restrict__ Vg, const int* __restrict__ amask,
    const int* __restrict__ mfp, float* __restrict__ Ctx)
{
    extern __shared__ float smf[];
    float* Qs = smf;
    float* Ks = Qs + FM * FP;
    float* Vs = Ks + FN * FP;
    float* Ps = Vs + FN * FP;
    int*   ms = (int*)(Ps + FM * FP);

    const int tid = threadIdx.x;
    const int tx = tid & 15, ty = tid >> 4;
    const int bh = blockIdx.y;
    const int b = bh >> 4, h = bh & 15;
    const int q0 = blockIdx.x * FM;
    const int causal = *mfp;
    const float scale = 0.125f;

    const float* Qbase = Qg + ((size_t)b * Sq + q0) * Dq + h * HDq;
    for (int idx = tid; idx < 64 * 16; idx += 256) {
        int r = idx >> 4, c4 = (idx & 15) << 2;
        *(float4*)&Qs[r * FP + c4] = *(const float4*)&Qbase[(size_t)r * Dq + c4];
    }

    float Ot[4][4];
    float mrow[4], lrow[4];
#pragma unroll
    for (int i = 0; i < 4; i++) {
        mrow[i] = -1e30f; lrow[i] = 0.0f;
#pragma unroll
        for (int j = 0; j < 4; j++) Ot[i][j] = 0.0f;
    }

    const int tEnd = causal ? (blockIdx.x + 1) : (Sq / FN);

    for (int tt = 0; tt < tEnd; tt++) {
        const int j0 = tt * FN;
        const float* Kbase = Kg + ((size_t)b * Sq + j0) * Dq + h * HDq;
        const float* Vbase = Vg + ((size_t)b * Sq + j0) * Dq + h * HDq;
        for (int idx = tid; idx < 64 * 16; idx += 256) {
            int r = idx >> 4, c4 = (idx & 15) << 2;
            *(float4*)&Ks[r * FP + c4] = *(const float4*)&Kbase[(size_t)r * Dq + c4];
            *(float4*)&Vs[r * FP + c4] = *(const float4*)&Vbase[(size_t)r * Dq + c4];
        }
        if (tid < FN) ms[tid] = amask[b * Sq + j0 + tid];
        __syncthreads();

        float s[4][4];
#pragma unroll
        for (int i = 0; i < 4; i++)
#pragma unroll
            for (int j = 0; j < 4; j++) s[i][j] = 0.0f;

#pragma unroll
        for (int d = 0; d < HDq; d += 4) {
            float4 qa[4], kb[4];
#pragma unroll
            for (int i = 0; i < 4; i++) qa[i] = *(const float4*)&Qs[(ty * 4 + i) * FP + d];
#pragma unroll
            for (int j = 0; j < 4; j++) kb[j] = *(const float4*)&Ks[(tx * 4 + j) * FP + d];
#pragma unroll
            for (int i = 0; i < 4; i++)
#pragma unroll
                for (int j = 0; j < 4; j++) {
                    s[i][j] = fmaf(qa[i].x, kb[j].x, s[i][j]);
                    s[i][j] = fmaf(qa[i].y, kb[j].y, s[i][j]);
                    s[i][j] = fmaf(qa[i].z, kb[j].z, s[i][j]);
                    s[i][j] = fmaf(qa[i].w, kb[j].w, s[i][j]);
                }
        }

#pragma unroll
        for (int i = 0; i < 4; i++) {
            const int rg = q0 + ty * 4 + i;
            float rmax = -1e30f;
#pragma unroll
            for (int j = 0; j < 4; j++) {
                const int jg = j0 + tx * 4 + j;
                const bool dead = (ms[tx * 4 + j] == 0) || (causal && jg > rg);
                float sv = dead ? -1e30f : s[i][j] * scale;
                s[i][j] = sv;
                rmax = fmaxf(rmax, sv);
            }
#pragma unroll
            for (int o = 8; o >= 1; o >>= 1)
                rmax = fmaxf(rmax, __shfl_xor_sync(0xffffffffu, rmax, o));

            const float mo = mrow[i];
            const float mn = fmaxf(mo, rmax);
            const float alpha = __expf(mo - mn);
            float rsum = 0.0f;
#pragma unroll
            for (int j = 0; j < 4; j++) {
                float p = (s[i][j] <= -1e29f) ? 0.0f : __expf(s[i][j] - mn);
                s[i][j] = p;
                rsum += p;
            }
#pragma unroll
            for (int o = 8; o >= 1; o >>= 1)
                rsum += __shfl_xor_sync(0xffffffffu, rsum, o);

            lrow[i] = lrow[i] * alpha + rsum;
            mrow[i] = mn;
#pragma unroll
            for (int d = 0; d < 4; d++) Ot[i][d] *= alpha;

            *(float4*)&Ps[(ty * 4 + i) * FP + tx * 4] =
                make_float4(s[i][0], s[i][1], s[i][2], s[i][3]);
        }
        __syncthreads();

        // O += P V (float4 P and V loads)
#pragma unroll 4
        for (int j4 = 0; j4 < FN; j4 += 4) {
            float4 p0 = *(const float4*)&Ps[(ty * 4 + 0) * FP + j4];
            float4 p1 = *(const float4*)&Ps[(ty * 4 + 1) * FP + j4];
            float4 p2 = *(const float4*)&Ps[(ty * 4 + 2) * FP + j4];
            float4 p3 = *(const float4*)&Ps[(ty * 4 + 3) * FP + j4];
            float4 v0 = *(const float4*)&Vs[(j4 + 0) * FP + tx * 4];
            float4 v1 = *(const float4*)&Vs[(j4 + 1) * FP + tx * 4];
            float4 v2 = *(const float4*)&Vs[(j4 + 2) * FP + tx * 4];
            float4 v3 = *(const float4*)&Vs[(j4 + 3) * FP + tx * 4];
            const float pr[4][4] = {{p0.x, p0.y, p0.z, p0.w},
                                    {p1.x, p1.y, p1.z, p1.w},
                                    {p2.x, p2.y, p2.z, p2.w},
                                    {p3.x, p3.y, p3.z, p3.w}};
            const float4 vv[4] = {v0, v1, v2, v3};
#pragma unroll
            for (int i = 0; i < 4; i++)
#pragma unroll
                for (int jj = 0; jj < 4; jj++) {
                    Ot[i][0] = fmaf(pr[i][jj], vv[jj].x, Ot[i][0]);
                    Ot[i][1] = fmaf(pr[i][jj], vv[jj].y, Ot[i][1]);
                    Ot[i][2] = fmaf(pr[i][jj], vv[jj].z, Ot[i][2]);
                    Ot[i][3] = fmaf(pr[i][jj], vv[jj].w, Ot[i][3]);
                }
        }
        __syncthreads();
    }

#pragma unroll
    for (int i = 0; i < 4; i++) {
        const float inv = (lrow[i] > 0.0f) ? (1.0f / lrow[i]) : 0.0f;
        const int rg = q0 + ty * 4 + i;
        float4 o4 = make_float4(Ot[i][0] * inv, Ot[i][1] * inv,
                                Ot[i][2] * inv, Ot[i][3] * inv);
        *(float4*)&Ctx[((size_t)b * Sq + rg) * Dq + h * HDq + tx * 4] = o4;
    }
}

// ---------------------------------------------------------------------------
// Exact cleanup for degenerate rows (all-padded causal prefix)
// ---------------------------------------------------------------------------
__global__ __launch_bounds__(256) void fix_degenerate(
    const float* __restrict__ Qg, const float* __restrict__ Kg,
    const float* __restrict__ Vg, const int* __restrict__ amask,
    const int* __restrict__ mfp, float* __restrict__ Ctx)
{
    const int b = blockIdx.x >> 4, h = blockIdx.x & 15;
    const int tid = threadIdx.x;
    const int causal = *mfp;

    __shared__ int   redi[256];
    __shared__ float redf[256];
    __shared__ float qrow[HDq];
    __shared__ float sc[Sq];

    int local = Sq;
    for (int s = tid; s < Sq; s += 256)
        if (amask[b * Sq + s]) local = min(local, s);
    redi[tid] = local;
    __syncthreads();
    for (int o = 128; o > 0; o >>= 1) {
        if (tid < o) redi[tid] = min(redi[tid], redi[tid + o]);
        __syncthreads();
    }
    const int s0 = redi[0];
    int nrows;
    if (causal) nrows = s0;
    else        nrows = (s0 == Sq) ? Sq : 0;
    if (nrows == 0) return;

    for (int i = 0; i < nrows; i++) {
        if (tid < HDq) qrow[tid] = Qg[((size_t)b * Sq + i) * Dq + h * HDq + tid];
        __syncthreads();

        for (int j = tid; j < Sq; j += 256) {
            const float* kr = Kg + ((size_t)b * Sq + j) * Dq + h * HDq;
            float acc = 0.0f;
#pragma unroll
            for (int d = 0; d < HDq; d++) acc = fmaf(qrow[d], kr[d], acc);
            float v = acc * 0.125f;
            if (causal && j > i) v += NEGB;
            if (amask[b * Sq + j] == 0) v = NEGB;
            sc[j] = v;
        }
        __syncthreads();

        float lm = -1e30f;
        for (int j = tid; j < Sq; j += 256) lm = fmaxf(lm, sc[j]);
        redf[tid] = lm; __syncthreads();
        for (int o = 128; o > 0; o >>= 1) {
            if (tid < o) redf[tid] = fmaxf(redf[tid], redf[tid + o]);
            __syncthreads();
        }
        const float m = redf[0];
        __syncthreads();

        float ls = 0.0f;
        for (int j = tid; j < Sq; j += 256) {
            float p = __expf(sc[j] - m);
            sc[j] = p;
            ls += p;
        }
        redf[tid] = ls; __syncthreads();
        for (int o = 128; o > 0; o >>= 1) {
            if (tid < o) redf[tid] += redf[tid + o];
            __syncthreads();
        }
        const float l = redf[0];
        __syncthreads();

        if (tid < HDq) {
            float acc = 0.0f;
            for (int j = 0; j < Sq; j++)
                acc = fmaf(sc[j], __ldg(&Vg[((size_t)b * Sq + j) * Dq + h * HDq + tid]), acc);
            Ctx[((size_t)b * Sq + i) * Dq + h * HDq + tid] = acc / l;
        }
        __syncthreads();
    }
}

// ---------------------------------------------------------------------------
// Launch
// ---------------------------------------------------------------------------
extern "C" void kernel_launch(void* const* d_in, const int* in_sizes, int n_in,
                              void* d_out, int out_size)
{
    const float* q     = (const float*)d_in[0];
    const float* k     = (const float*)d_in[1];
    const float* v     = (const float*)d_in[2];
    const int*   amask = (const int*)  d_in[3];
    const float* Wq    = (const float*)d_in[4];
    const float* Wk    = (const float*)d_in[5];
    const float* Wv    = (const float*)d_in[6];
    const float* Wo    = (const float*)d_in[7];
    const int*   mf    = (const int*)  d_in[8];
    float*       out   = (float*)d_out;

    float *gQ, *gK, *gV, *gC;
    cudaGetSymbolAddress((void**)&gQ, g_Q);
    cudaGetSymbolAddress((void**)&gK, g_K);
    cudaGetSymbolAddress((void**)&gV, g_V);
    cudaGetSymbolAddress((void**)&gC, g_C);

    cudaFuncSetAttribute(gemm_tf32, cudaFuncAttributeMaxDynamicSharedMemorySize,
                         (int)GEMM_SMEM);

    const int M = Bq * Sq;                    // 4096
    const dim3 gg(Dq / BN, M / BM);           // (8, 32)

    gemm_tf32<<<gg, 256, GEMM_SMEM>>>(q, Wq, gQ, M);
    gemm_tf32<<<gg, 256, GEMM_SMEM>>>(k, Wk, gK, M);
    gemm_tf32<<<gg, 256, GEMM_SMEM>>>(v, Wv, gV, M);

    const size_t fsm = (size_t)(4 * FM * FP) * sizeof(float) + FN * sizeof(int);
    cudaFuncSetAttribute(flash_kernel, cudaFuncAttributeMaxDynamicSharedMemorySize, (int)fsm);
    flash_kernel<<<dim3(Sq / FM, Bq * Hq), 256, fsm>>>(gQ, gK, gV, amask, mf, gC);
    fix_degenerate<<<Bq * Hq, 256>>>(gQ, gK, gV, amask, mf, gC);

    gemm_tf32<<<gg, 256, GEMM_SMEM>>>(gC, Wo, out, M);
}

// round 4
// speedup vs baseline: 2.1944x; 1.6293x over previous
#include <cuda_runtime.h>
#include <math.h>
#include <stdint.h>

// Problem constants
constexpr int Bq  = 2;
constexpr int Sq  = 2048;
constexpr int Dq  = 1024;
constexpr int Hq  = 16;
constexpr int HDq = 64;
constexpr float NEGB = -10000.0f;

// ---------------------------------------------------------------------------
// Scratch (device globals: no allocation allowed)
// ---------------------------------------------------------------------------
__device__ __align__(16) float g_Q[Bq * Sq * Dq];
__device__ __align__(16) float g_K[Bq * Sq * Dq];
__device__ __align__(16) float g_V[Bq * Sq * Dq];
__device__ __align__(16) float g_C[Bq * Sq * Dq];

// ---------------------------------------------------------------------------
// Helpers
// ---------------------------------------------------------------------------
__device__ __forceinline__ uint32_t rtf32_bits(float x) {
    uint32_t u;
    asm("cvt.rna.tf32.f32 %0, %1;" : "=r"(u) : "f"(x));
    return u;
}
__device__ __forceinline__ float rtf32(float x) {
    return __uint_as_float(rtf32_bits(x));
}

__device__ __forceinline__ void mma_tf32(
    float& c0, float& c1, float& c2, float& c3,
    uint32_t a0, uint32_t a1, uint32_t a2, uint32_t a3,
    uint32_t b0, uint32_t b1)
{
    asm volatile(
        "mma.sync.aligned.m16n8k8.row.col.f32.tf32.tf32.f32 "
        "{%0,%1,%2,%3}, {%4,%5,%6,%7}, {%8,%9}, {%0,%1,%2,%3};"
        : "+f"(c0), "+f"(c1), "+f"(c2), "+f"(c3)
        : "r"(a0), "r"(a1), "r"(a2), "r"(a3), "r"(b0), "r"(b1));
}

__device__ __forceinline__ uint32_t smem_u32(const void* p) {
    uint32_t a;
    asm("{ .reg .u64 t; cvta.to.shared.u64 t, %1; cvt.u32.u64 %0, t; }"
        : "=r"(a) : "l"(p));
    return a;
}

__device__ __forceinline__ void cp_async16(uint32_t dst, const void* src) {
    asm volatile("cp.async.cg.shared.global [%0], [%1], 16;"
                 :: "r"(dst), "l"(src) : "memory");
}
__device__ __forceinline__ void cp_commit() {
    asm volatile("cp.async.commit_group;" ::: "memory");
}
template <int N>
__device__ __forceinline__ void cp_wait() {
    asm volatile("cp.async.wait_group %0;" :: "n"(N) : "memory");
}

// ---------------------------------------------------------------------------
// tf32 mma.sync GEMM (unchanged from round 3, verified 5.4e-4)
// ---------------------------------------------------------------------------
constexpr int BM = 128, BN = 128, BK = 32;
constexpr int SSTR = 40;
constexpr int OPF  = BM * SSTR;
constexpr uint32_t GEMM_SMEM = 2 * 2 * OPF * 4;

__device__ __forceinline__ int kperm(int k) {
    return (k & 24) + ((k & 3) << 1) + ((k & 4) >> 2);
}

__global__ __launch_bounds__(256) void gemm_tf32(
    const float* __restrict__ A, const float* __restrict__ Wt,
    float* __restrict__ C, int M)
{
    extern __shared__ __align__(16) float sm[];
    const int tid  = threadIdx.x;
    const int lane = tid & 31;
    const int wid  = tid >> 5;
    const int g    = lane >> 2;
    const int t    = lane & 3;
    const int wm0  = (wid & 1) * 64;
    const int wn0  = (wid >> 1) * 32;
    const int m0   = blockIdx.y * BM;
    const int n0   = blockIdx.x * BN;

    const int c4  = tid & 7;
    const int r0  = tid >> 3;
    const float* Ag = A  + (size_t)m0 * Dq + c4 * 4;
    const float* Bg = Wt + (size_t)n0 * Dq + c4 * 4;

    float cr[4][4][4];
#pragma unroll
    for (int i = 0; i < 4; i++)
#pragma unroll
        for (int j = 0; j < 4; j++)
#pragma unroll
            for (int e = 0; e < 4; e++) cr[i][j][e] = 0.0f;

    float4 apf[4], bpf[4];

    auto ldg_chunk = [&](int kc) {
#pragma unroll
        for (int i = 0; i < 4; i++) {
            apf[i] = *(const float4*)(Ag + (size_t)(r0 + 32 * i) * Dq + kc);
            bpf[i] = *(const float4*)(Bg + (size_t)(r0 + 32 * i) * Dq + kc);
        }
    };
    auto sts_chunk = [&](int s) {
        float* As = sm + s * 2 * OPF;
        float* Bs = As + OPF;
#pragma unroll
        for (int i = 0; i < 4; i++) {
            const int row = r0 + 32 * i;
            const float av[4] = {apf[i].x, apf[i].y, apf[i].z, apf[i].w};
            const float bv[4] = {bpf[i].x, bpf[i].y, bpf[i].z, bpf[i].w};
#pragma unroll
            for (int e = 0; e < 4; e++) {
                const int p = kperm(c4 * 4 + e);
                As[row * SSTR + p] = rtf32(av[e]);
                Bs[row * SSTR + p] = rtf32(bv[e]);
            }
        }
    };
    auto mma_chunk = [&](int s) {
        const float* As = sm + s * 2 * OPF;
        const float* Bs = As + OPF;
#pragma unroll
        for (int kk = 0; kk < BK; kk += 8) {
            uint32_t af[4][4];
            uint32_t bf[4][2];
#pragma unroll
            for (int mt = 0; mt < 4; mt++) {
                const int row = wm0 + mt * 16 + g;
                float2 lo = *(const float2*)&As[row * SSTR + kk + 2 * t];
                float2 hi = *(const float2*)&As[(row + 8) * SSTR + kk + 2 * t];
                af[mt][0] = __float_as_uint(lo.x);
                af[mt][2] = __float_as_uint(lo.y);
                af[mt][1] = __float_as_uint(hi.x);
                af[mt][3] = __float_as_uint(hi.y);
            }
#pragma unroll
            for (int nt = 0; nt < 4; nt++) {
                const int row = wn0 + nt * 8 + g;
                float2 bb = *(const float2*)&Bs[row * SSTR + kk + 2 * t];
                bf[nt][0] = __float_as_uint(bb.x);
                bf[nt][1] = __float_as_uint(bb.y);
            }
#pragma unroll
            for (int mt = 0; mt < 4; mt++)
#pragma unroll
                for (int nt = 0; nt < 4; nt++)
                    mma_tf32(cr[mt][nt][0], cr[mt][nt][1],
                             cr[mt][nt][2], cr[mt][nt][3],
                             af[mt][0], af[mt][1], af[mt][2], af[mt][3],
                             bf[nt][0], bf[nt][1]);
        }
    };

    constexpr int NCH = Dq / BK;
    ldg_chunk(0);
    sts_chunk(0);
    __syncthreads();
    for (int c = 0; c < NCH; c++) {
        if (c + 1 < NCH) ldg_chunk((c + 1) * BK);
        mma_chunk(c & 1);
        __syncthreads();
        if (c + 1 < NCH) {
            sts_chunk((c + 1) & 1);
            __syncthreads();
        }
    }

#pragma unroll
    for (int mt = 0; mt < 4; mt++) {
#pragma unroll
        for (int nt = 0; nt < 4; nt++) {
            const int row = m0 + wm0 + mt * 16 + g;
            const int col = n0 + wn0 + nt * 8 + 2 * t;
            *(float2*)&C[(size_t)row * Dq + col] =
                make_float2(cr[mt][nt][0], cr[mt][nt][1]);
            *(float2*)&C[(size_t)(row + 8) * Dq + col] =
                make_float2(cr[mt][nt][2], cr[mt][nt][3]);
        }
    }
}

// ---------------------------------------------------------------------------
// Tensor-core flash attention.
// CTA: 256 threads (8 warps), 128 q-rows, 64 keys per iteration, HD=64.
// S = Q K^T via 3xTF32 split mma (fp32-grade accuracy); PV via plain tf32.
// K/V tiles double-buffered with cp.async. P routed warp-privately via smem.
// ---------------------------------------------------------------------------
constexpr int FMr = 128, FNr = 64, FST = 68;     // row stride 68 floats (16B-mult)
constexpr int KV_FLOATS = 64 * FST;              // one K or V stage
constexpr uint32_t FL_SMEM =
    (2 * KV_FLOATS + 2 * KV_FLOATS + FMr * FST) * 4 + 2 * 64 * 4;

__global__ __launch_bounds__(256, 1) void flash_mma(
    const float* __restrict__ Qg, const float* __restrict__ Kg,
    const float* __restrict__ Vg, const int* __restrict__ amask,
    const int* __restrict__ mfp, float* __restrict__ Ctx)
{
    extern __shared__ __align__(16) float fs[];
    float* Kb = fs;                          // [2][64][FST]
    float* Vb = Kb + 2 * KV_FLOATS;          // [2][64][FST]
    float* Pb = Vb + 2 * KV_FLOATS;          // [128][FST] (Q staging, then P)
    int*   msb = (int*)(Pb + FMr * FST);     // [2][64]

    const int tid  = threadIdx.x;
    const int lane = tid & 31;
    const int w    = tid >> 5;
    const int g    = lane >> 2;
    const int t    = lane & 3;
    const int b    = blockIdx.y >> 4, h = blockIdx.y & 15;
    const int qb   = gridDim.x - 1 - blockIdx.x;   // heavy blocks first
    const int q0   = qb * FMr;
    const int causal = *mfp;
    const int nT   = causal ? 2 * (qb + 1) : (Sq / FNr);

    const float* Qbase = Qg + ((size_t)b * Sq + q0) * Dq + h * HDq;
    const float* Kbase = Kg + (size_t)b * Sq * Dq + h * HDq;
    const float* Vbase = Vg + (size_t)b * Sq * Dq + h * HDq;
    const int*   mbase = amask + b * Sq;

    // ---- stage Q into Pb, load Q fragments (hi/lo split) ----
    for (int e = tid; e < FMr * 16; e += 256) {
        int r = e >> 4, c4 = (e & 15) << 2;
        *(float4*)&Pb[r * FST + c4] = *(const float4*)&Qbase[(size_t)r * Dq + c4];
    }
    __syncthreads();

    const int rA = w * 16 + g;                 // warp-local row A (B = +8)
    uint32_t qhi[8][4], qlo[8][4];
#pragma unroll
    for (int kk = 0; kk < 8; kk++) {
        float v0 = Pb[rA * FST + kk * 8 + t];
        float v1 = Pb[(rA + 8) * FST + kk * 8 + t];
        float v2 = Pb[rA * FST + kk * 8 + t + 4];
        float v3 = Pb[(rA + 8) * FST + kk * 8 + t + 4];
        qhi[kk][0] = rtf32_bits(v0); qlo[kk][0] = rtf32_bits(v0 - __uint_as_float(qhi[kk][0]));
        qhi[kk][1] = rtf32_bits(v1); qlo[kk][1] = rtf32_bits(v1 - __uint_as_float(qhi[kk][1]));
        qhi[kk][2] = rtf32_bits(v2); qlo[kk][2] = rtf32_bits(v2 - __uint_as_float(qhi[kk][2]));
        qhi[kk][3] = rtf32_bits(v3); qlo[kk][3] = rtf32_bits(v3 - __uint_as_float(qhi[kk][3]));
    }

    const uint32_t Kb_u = smem_u32(Kb);
    const uint32_t Vb_u = smem_u32(Vb);

    auto prefetch = [&](int j, int s) {
        const float* Ksrc = Kbase + (size_t)(j * FNr) * Dq;
        const float* Vsrc = Vbase + (size_t)(j * FNr) * Dq;
        const uint32_t kd = Kb_u + (uint32_t)s * KV_FLOATS * 4;
        const uint32_t vd = Vb_u + (uint32_t)s * KV_FLOATS * 4;
#pragma unroll
        for (int i = 0; i < 4; i++) {
            const int e = i * 256 + tid;
            const int r = e >> 4, c4 = (e & 15) << 2;
            cp_async16(kd + (uint32_t)(r * FST + c4) * 4, Ksrc + (size_t)r * Dq + c4);
            cp_async16(vd + (uint32_t)(r * FST + c4) * 4, Vsrc + (size_t)r * Dq + c4);
        }
        if (tid < 64) msb[s * 64 + tid] = mbase[j * FNr + tid];
        cp_commit();
    };

    float O[8][4];
#pragma unroll
    for (int nt = 0; nt < 8; nt++)
#pragma unroll
        for (int e = 0; e < 4; e++) O[nt][e] = 0.0f;
    float mAr = -1e30f, mBr = -1e30f, lAr = 0.0f, lBr = 0.0f;

    const int rgA = q0 + rA;
    const int rgB = rgA + 8;

    prefetch(0, 0);

    for (int j = 0; j < nT; j++) {
        if (j + 1 < nT) { prefetch(j + 1, (j + 1) & 1); cp_wait<1>(); }
        else            { cp_wait<0>(); }
        __syncthreads();

        const int s = j & 1;
        const float* kd = Kb + s * KV_FLOATS;
        const float* vd = Vb + s * KV_FLOATS;
        const int*   ml = msb + s * 64;
        const int j0 = j * FNr;

        // ---- S = Q K^T (3xTF32) ----
        float Sv[8][4];
#pragma unroll
        for (int nt = 0; nt < 8; nt++)
#pragma unroll
            for (int e = 0; e < 4; e++) Sv[nt][e] = 0.0f;

#pragma unroll
        for (int kk = 0; kk < 8; kk++) {
#pragma unroll
            for (int nt = 0; nt < 8; nt++) {
                const float b0 = kd[(nt * 8 + g) * FST + kk * 8 + t];
                const float b1 = kd[(nt * 8 + g) * FST + kk * 8 + t + 4];
                const uint32_t bh0 = rtf32_bits(b0);
                const uint32_t bh1 = rtf32_bits(b1);
                const uint32_t bl0 = rtf32_bits(b0 - __uint_as_float(bh0));
                const uint32_t bl1 = rtf32_bits(b1 - __uint_as_float(bh1));
                mma_tf32(Sv[nt][0], Sv[nt][1], Sv[nt][2], Sv[nt][3],
                         qhi[kk][0], qhi[kk][1], qhi[kk][2], qhi[kk][3], bl0, bl1);
                mma_tf32(Sv[nt][0], Sv[nt][1], Sv[nt][2], Sv[nt][3],
                         qlo[kk][0], qlo[kk][1], qlo[kk][2], qlo[kk][3], bh0, bh1);
                mma_tf32(Sv[nt][0], Sv[nt][1], Sv[nt][2], Sv[nt][3],
                         qhi[kk][0], qhi[kk][1], qhi[kk][2], qhi[kk][3], bh0, bh1);
            }
        }

        // ---- mask + scale ----
        float rmA = -1e30f, rmB = -1e30f;
#pragma unroll
        for (int nt = 0; nt < 8; nt++) {
            const int2 mm = *(const int2*)&ml[nt * 8 + 2 * t];
            const int c0g = j0 + nt * 8 + 2 * t;
            const int c1g = c0g + 1;
            const bool d0 = (mm.x == 0), d1 = (mm.y == 0);
            Sv[nt][0] = (d0 || (causal && c0g > rgA)) ? -1e30f : Sv[nt][0] * 0.125f;
            Sv[nt][1] = (d1 || (causal && c1g > rgA)) ? -1e30f : Sv[nt][1] * 0.125f;
            Sv[nt][2] = (d0 || (causal && c0g > rgB)) ? -1e30f : Sv[nt][2] * 0.125f;
            Sv[nt][3] = (d1 || (causal && c1g > rgB)) ? -1e30f : Sv[nt][3] * 0.125f;
            rmA = fmaxf(rmA, fmaxf(Sv[nt][0], Sv[nt][1]));
            rmB = fmaxf(rmB, fmaxf(Sv[nt][2], Sv[nt][3]));
        }
        rmA = fmaxf(rmA, __shfl_xor_sync(0xffffffffu, rmA, 1));
        rmA = fmaxf(rmA, __shfl_xor_sync(0xffffffffu, rmA, 2));
        rmB = fmaxf(rmB, __shfl_xor_sync(0xffffffffu, rmB, 1));
        rmB = fmaxf(rmB, __shfl_xor_sync(0xffffffffu, rmB, 2));

        const float mnA = fmaxf(mAr, rmA);
        const float mnB = fmaxf(mBr, rmB);
        const float aA = __expf(mAr - mnA);
        const float aB = __expf(mBr - mnB);

        float sA = 0.0f, sB = 0.0f;
#pragma unroll
        for (int nt = 0; nt < 8; nt++) {
            float p0 = (Sv[nt][0] <= -1e29f) ? 0.0f : __expf(Sv[nt][0] - mnA);
            float p1 = (Sv[nt][1] <= -1e29f) ? 0.0f : __expf(Sv[nt][1] - mnA);
            float p2 = (Sv[nt][2] <= -1e29f) ? 0.0f : __expf(Sv[nt][2] - mnB);
            float p3 = (Sv[nt][3] <= -1e29f) ? 0.0f : __expf(Sv[nt][3] - mnB);
            Sv[nt][0] = p0; Sv[nt][1] = p1; Sv[nt][2] = p2; Sv[nt][3] = p3;
            sA += p0 + p1; sB += p2 + p3;
        }
        sA += __shfl_xor_sync(0xffffffffu, sA, 1);
        sA += __shfl_xor_sync(0xffffffffu, sA, 2);
        sB += __shfl_xor_sync(0xffffffffu, sB, 1);
        sB += __shfl_xor_sync(0xffffffffu, sB, 2);

        lAr = lAr * aA + sA; mAr = mnA;
        lBr = lBr * aB + sB; mBr = mnB;

#pragma unroll
        for (int nt = 0; nt < 8; nt++) {
            O[nt][0] *= aA; O[nt][1] *= aA;
            O[nt][2] *= aB; O[nt][3] *= aB;
            *(float2*)&Pb[rA * FST + nt * 8 + 2 * t] = make_float2(Sv[nt][0], Sv[nt][1]);
            *(float2*)&Pb[(rA + 8) * FST + nt * 8 + 2 * t] = make_float2(Sv[nt][2], Sv[nt][3]);
        }
        __syncwarp();

        // ---- O += P V (plain tf32) ----
#pragma unroll
        for (int kk = 0; kk < 8; kk++) {
            const uint32_t a0 = rtf32_bits(Pb[rA * FST + kk * 8 + t]);
            const uint32_t a1 = rtf32_bits(Pb[(rA + 8) * FST + kk * 8 + t]);
            const uint32_t a2 = rtf32_bits(Pb[rA * FST + kk * 8 + t + 4]);
            const uint32_t a3 = rtf32_bits(Pb[(rA + 8) * FST + kk * 8 + t + 4]);
#pragma unroll
            for (int nt = 0; nt < 8; nt++) {
                const uint32_t b0 = rtf32_bits(vd[(kk * 8 + t) * FST + nt * 8 + g]);
                const uint32_t b1 = rtf32_bits(vd[(kk * 8 + t + 4) * FST + nt * 8 + g]);
                mma_tf32(O[nt][0], O[nt][1], O[nt][2], O[nt][3],
                         a0, a1, a2, a3, b0, b1);
            }
        }
        __syncthreads();
    }

    // ---- epilogue ----
    const float iA = (lAr > 0.0f) ? (1.0f / lAr) : 0.0f;
    const float iB = (lBr > 0.0f) ? (1.0f / lBr) : 0.0f;
    float* CA = Ctx + ((size_t)b * Sq + rgA) * Dq + h * HDq;
    float* CB = Ctx + ((size_t)b * Sq + rgB) * Dq + h * HDq;
#pragma unroll
    for (int nt = 0; nt < 8; nt++) {
        *(float2*)&CA[nt * 8 + 2 * t] = make_float2(O[nt][0] * iA, O[nt][1] * iA);
        *(float2*)&CB[nt * 8 + 2 * t] = make_float2(O[nt][2] * iB, O[nt][3] * iB);
    }
}

// ---------------------------------------------------------------------------
// Exact cleanup for degenerate rows (all-padded causal prefix)
// ---------------------------------------------------------------------------
__global__ __launch_bounds__(256) void fix_degenerate(
    const float* __restrict__ Qg, const float* __restrict__ Kg,
    const float* __restrict__ Vg, const int* __restrict__ amask,
    const int* __restrict__ mfp, float* __restrict__ Ctx)
{
    const int b = blockIdx.x >> 4, h = blockIdx.x & 15;
    const int tid = threadIdx.x;
    const int causal = *mfp;

    __shared__ int   redi[256];
    __shared__ float redf[256];
    __shared__ float qrow[HDq];
    __shared__ float sc[Sq];

    int local = Sq;
    for (int s = tid; s < Sq; s += 256)
        if (amask[b * Sq + s]) local = min(local, s);
    redi[tid] = local;
    __syncthreads();
    for (int o = 128; o > 0; o >>= 1) {
        if (tid < o) redi[tid] = min(redi[tid], redi[tid + o]);
        __syncthreads();
    }
    const int s0 = redi[0];
    int nrows;
    if (causal) nrows = s0;
    else        nrows = (s0 == Sq) ? Sq : 0;
    if (nrows == 0) return;

    for (int i = 0; i < nrows; i++) {
        if (tid < HDq) qrow[tid] = Qg[((size_t)b * Sq + i) * Dq + h * HDq + tid];
        __syncthreads();

        for (int j = tid; j < Sq; j += 256) {
            const float* kr = Kg + ((size_t)b * Sq + j) * Dq + h * HDq;
            float acc = 0.0f;
#pragma unroll
            for (int d = 0; d < HDq; d++) acc = fmaf(qrow[d], kr[d], acc);
            float v = acc * 0.125f;
            if (causal && j > i) v += NEGB;
            if (amask[b * Sq + j] == 0) v = NEGB;
            sc[j] = v;
        }
        __syncthreads();

        float lm = -1e30f;
        for (int j = tid; j < Sq; j += 256) lm = fmaxf(lm, sc[j]);
        redf[tid] = lm; __syncthreads();
        for (int o = 128; o > 0; o >>= 1) {
            if (tid < o) redf[tid] = fmaxf(redf[tid], redf[tid + o]);
            __syncthreads();
        }
        const float m = redf[0];
        __syncthreads();

        float ls = 0.0f;
        for (int j = tid; j < Sq; j += 256) {
            float p = __expf(sc[j] - m);
            sc[j] = p;
            ls += p;
        }
        redf[tid] = ls; __syncthreads();
        for (int o = 128; o > 0; o >>= 1) {
            if (tid < o) redf[tid] += redf[tid + o];
            __syncthreads();
        }
        const float l = redf[0];
        __syncthreads();

        if (tid < HDq) {
            float acc = 0.0f;
            for (int j = 0; j < Sq; j++)
                acc = fmaf(sc[j], __ldg(&Vg[((size_t)b * Sq + j) * Dq + h * HDq + tid]), acc);
            Ctx[((size_t)b * Sq + i) * Dq + h * HDq + tid] = acc / l;
        }
        __syncthreads();
    }
}

// ---------------------------------------------------------------------------
// Launch
// ---------------------------------------------------------------------------
extern "C" void kernel_launch(void* const* d_in, const int* in_sizes, int n_in,
                              void* d_out, int out_size)
{
    const float* q     = (const float*)d_in[0];
    const float* k     = (const float*)d_in[1];
    const float* v     = (const float*)d_in[2];
    const int*   amask = (const int*)  d_in[3];
    const float* Wq    = (const float*)d_in[4];
    const float* Wk    = (const float*)d_in[5];
    const float* Wv    = (const float*)d_in[6];
    const float* Wo    = (const float*)d_in[7];
    const int*   mf    = (const int*)  d_in[8];
    float*       out   = (float*)d_out;

    float *gQ, *gK, *gV, *gC;
    cudaGetSymbolAddress((void**)&gQ, g_Q);
    cudaGetSymbolAddress((void**)&gK, g_K);
    cudaGetSymbolAddress((void**)&gV, g_V);
    cudaGetSymbolAddress((void**)&gC, g_C);

    cudaFuncSetAttribute(gemm_tf32, cudaFuncAttributeMaxDynamicSharedMemorySize,
                         (int)GEMM_SMEM);
    cudaFuncSetAttribute(flash_mma, cudaFuncAttributeMaxDynamicSharedMemorySize,
                         (int)FL_SMEM);

    const int M = Bq * Sq;                    // 4096
    const dim3 gg(Dq / BN, M / BM);           // (8, 32)

    gemm_tf32<<<gg, 256, GEMM_SMEM>>>(q, Wq, gQ, M);
    gemm_tf32<<<gg, 256, GEMM_SMEM>>>(k, Wk, gK, M);
    gemm_tf32<<<gg, 256, GEMM_SMEM>>>(v, Wv, gV, M);

    flash_mma<<<dim3(Sq / FMr, Bq * Hq), 256, FL_SMEM>>>(gQ, gK, gV, amask, mf, gC);
    fix_degenerate<<<Bq * Hq, 256>>>(gQ, gK, gV, amask, mf, gC);

    gemm_tf32<<<gg, 256, GEMM_SMEM>>>(gC, Wo, out, M);
}

// round 6
// speedup vs baseline: 2.3963x; 1.0920x over previous
#include <cuda_runtime.h>
#include <math.h>
#include <stdint.h>

// Problem constants
constexpr int Bq  = 2;
constexpr int Sq  = 2048;
constexpr int Dq  = 1024;
constexpr int Hq  = 16;
constexpr int HDq = 64;
constexpr float NEGB = -10000.0f;

// ---------------------------------------------------------------------------
// Scratch (device globals: no allocation allowed)
// ---------------------------------------------------------------------------
__device__ __align__(16) float g_Q[Bq * Sq * Dq];
__device__ __align__(16) float g_K[Bq * Sq * Dq];
__device__ __align__(16) float g_V[Bq * Sq * Dq];
__device__ __align__(16) float g_C[Bq * Sq * Dq];
__device__ __align__(16) float g_A[Bq * Sq * Dq];   // tf32-rounded activation
__device__ __align__(16) float g_W[Dq * Dq];        // tf32-rounded weight

// ---------------------------------------------------------------------------
// Helpers
// ---------------------------------------------------------------------------
__device__ __forceinline__ uint32_t rtf32_bits(float x) {
    uint32_t u;
    asm("cvt.rna.tf32.f32 %0, %1;" : "=r"(u) : "f"(x));
    return u;
}
__device__ __forceinline__ float rtf32(float x) {
    return __uint_as_float(rtf32_bits(x));
}

__global__ __launch_bounds__(256) void round_tf32_kernel(
    const float* __restrict__ in, float* __restrict__ out, int n4)
{
    int i = blockIdx.x * blockDim.x + threadIdx.x;
    if (i < n4) {
        float4 v = ((const float4*)in)[i];
        float4 o;
        o.x = rtf32(v.x); o.y = rtf32(v.y); o.z = rtf32(v.z); o.w = rtf32(v.w);
        ((float4*)out)[i] = o;
    }
}

__device__ __forceinline__ void mma_tf32(
    float& c0, float& c1, float& c2, float& c3,
    uint32_t a0, uint32_t a1, uint32_t a2, uint32_t a3,
    uint32_t b0, uint32_t b1)
{
    asm volatile(
        "mma.sync.aligned.m16n8k8.row.col.f32.tf32.tf32.f32 "
        "{%0,%1,%2,%3}, {%4,%5,%6,%7}, {%8,%9}, {%0,%1,%2,%3};"
        : "+f"(c0), "+f"(c1), "+f"(c2), "+f"(c3)
        : "r"(a0), "r"(a1), "r"(a2), "r"(a3), "r"(b0), "r"(b1));
}

__device__ __forceinline__ uint32_t smem_u32(const void* p) {
    uint32_t a;
    asm("{ .reg .u64 t; cvta.to.shared.u64 t, %1; cvt.u32.u64 %0, t; }"
        : "=r"(a) : "l"(p));
    return a;
}

__device__ __forceinline__ void cp_async16(uint32_t dst, const void* src) {
    asm volatile("cp.async.cg.shared.global [%0], [%1], 16;"
                 :: "r"(dst), "l"(src) : "memory");
}
__device__ __forceinline__ void cp_commit() {
    asm volatile("cp.async.commit_group;" ::: "memory");
}
template <int N>
__device__ __forceinline__ void cp_wait() {
    asm volatile("cp.async.wait_group %0;" :: "n"(N) : "memory");
}

// ---------------------------------------------------------------------------
// tf32 mma.sync GEMM: C[M,N] = A[M,K] @ W[N,K]^T, fp32 accumulate.
// Inputs MUST be pre-rounded to tf32 in global memory.
// CTA 128x128, BK=32, 3-stage cp.async pipeline, 1 syncthreads per chunk.
// Smem: plain row-major, pad stride 36 floats (conflict-free LDS.32 frags).
// ---------------------------------------------------------------------------
constexpr int GP   = 36;                      // smem row stride (floats)
constexpr int STGF = 128 * GP;                // floats per operand-stage
constexpr int NSTG = 3;
constexpr uint32_t GEMM_SMEM = NSTG * 2 * STGF * 4;  // 110592 B

__global__ __launch_bounds__(256) void gemm_tf32(
    const float* __restrict__ A, const float* __restrict__ Wt,
    float* __restrict__ C)
{
    extern __shared__ __align__(16) float sm[];
    const int tid  = threadIdx.x;
    const int lane = tid & 31;
    const int wid  = tid >> 5;
    const int g    = lane >> 2;
    const int t    = lane & 3;
    const int wm0  = (wid & 1) * 64;
    const int wn0  = (wid >> 1) * 32;
    const int m0   = blockIdx.y * 128;
    const int n0   = blockIdx.x * 128;
    const uint32_t sm_u = smem_u32(sm);

    auto prefetch = [&](int c, int s) {
        const int kc = c * 32;
        const uint32_t as = sm_u + (uint32_t)(s * 2 * STGF) * 4;
        const uint32_t bs = as + (uint32_t)STGF * 4;
#pragma unroll
        for (int i = 0; i < 4; i++) {
            const int id = i * 256 + tid;
            const int rr = id >> 3;
            const int c4 = (id & 7) * 4;
            cp_async16(as + (uint32_t)(rr * GP + c4) * 4,
                       A + (size_t)(m0 + rr) * Dq + kc + c4);
            cp_async16(bs + (uint32_t)(rr * GP + c4) * 4,
                       Wt + (size_t)(n0 + rr) * Dq + kc + c4);
        }
        cp_commit();
    };

    float cr[4][4][4];
#pragma unroll
    for (int i = 0; i < 4; i++)
#pragma unroll
        for (int j = 0; j < 4; j++)
#pragma unroll
            for (int e = 0; e < 4; e++) cr[i][j][e] = 0.0f;

    prefetch(0, 0);
    prefetch(1, 1);

    constexpr int NCH = Dq / 32;   // 32
    for (int c = 0; c < NCH; c++) {
        if (c == NCH - 1) cp_wait<0>(); else cp_wait<1>();
        __syncthreads();
        if (c + 2 < NCH) prefetch(c + 2, (c + 2) % NSTG);

        const float* As = sm + (c % NSTG) * 2 * STGF;
        const float* Bs = As + STGF;
#pragma unroll
        for (int kk = 0; kk < 32; kk += 8) {
            uint32_t af[4][4], bf[4][2];
#pragma unroll
            for (int mt = 0; mt < 4; mt++) {
                const int row = wm0 + mt * 16 + g;
                af[mt][0] = __float_as_uint(As[row * GP + kk + t]);
                af[mt][1] = __float_as_uint(As[(row + 8) * GP + kk + t]);
                af[mt][2] = __float_as_uint(As[row * GP + kk + t + 4]);
                af[mt][3] = __float_as_uint(As[(row + 8) * GP + kk + t + 4]);
            }
#pragma unroll
            for (int nt = 0; nt < 4; nt++) {
                const int row = wn0 + nt * 8 + g;
                bf[nt][0] = __float_as_uint(Bs[row * GP + kk + t]);
                bf[nt][1] = __float_as_uint(Bs[row * GP + kk + t + 4]);
            }
#pragma unroll
            for (int mt = 0; mt < 4; mt++)
#pragma unroll
                for (int nt = 0; nt < 4; nt++)
                    mma_tf32(cr[mt][nt][0], cr[mt][nt][1],
                             cr[mt][nt][2], cr[mt][nt][3],
                             af[mt][0], af[mt][1], af[mt][2], af[mt][3],
                             bf[nt][0], bf[nt][1]);
        }
    }

#pragma unroll
    for (int mt = 0; mt < 4; mt++) {
#pragma unroll
        for (int nt = 0; nt < 4; nt++) {
            const int row = m0 + wm0 + mt * 16 + g;
            const int col = n0 + wn0 + nt * 8 + 2 * t;
            *(float2*)&C[(size_t)row * Dq + col] =
                make_float2(cr[mt][nt][0], cr[mt][nt][1]);
            *(float2*)&C[(size_t)(row + 8) * Dq + col] =
                make_float2(cr[mt][nt][2], cr[mt][nt][3]);
        }
    }
}

// ---------------------------------------------------------------------------
// Tensor-core flash attention, hoisted conversions.
// CTA: 256 threads (8 warps), 128 q-rows, 64 keys/iter, HD=64.
// Per stage: cp.async raw K/V (double-buffered) -> convert pass writes
//   Khl: interleaved (hi,lo) tf32 pairs, stride 136 (LDS.64 frag loads)
//   Vr : tf32-rounded V, stride 72 (conflict-free LDS.32)
// S = 3xTF32 split mma; P stored pre-rounded; PV plain tf32 mma.
// ---------------------------------------------------------------------------
constexpr int FMr = 128, FNr = 64;
constexpr int KRST = 68, VRST = 72, KHLST = 136, PST = 68;
constexpr int OFF_KRAW = 0;                         // [2][64*68]
constexpr int OFF_VRAW = OFF_KRAW + 2 * 64 * KRST;  // [2][64*72]
constexpr int OFF_KHL  = OFF_VRAW + 2 * 64 * VRST;  // [64*136]
constexpr int OFF_VR   = OFF_KHL + 64 * KHLST;      // [64*72]
constexpr int OFF_PB   = OFF_VR + 64 * VRST;        // [128*68]
constexpr int FL_FLOATS = OFF_PB + FMr * PST;
constexpr uint32_t FL_SMEM = FL_FLOATS * 4 + 2 * 64 * 4;

__global__ __launch_bounds__(256, 1) void flash_mma(
    const float* __restrict__ Qg, const float* __restrict__ Kg,
    const float* __restrict__ Vg, const int* __restrict__ amask,
    const int* __restrict__ mfp, float* __restrict__ Ctx)
{
    extern __shared__ __align__(16) float fs[];
    float* Kraw = fs + OFF_KRAW;
    float* Vraw = fs + OFF_VRAW;
    float* Khl  = fs + OFF_KHL;
    float* Vr   = fs + OFF_VR;
    float* Pb   = fs + OFF_PB;
    int*   msb  = (int*)(fs + FL_FLOATS);

    const int tid  = threadIdx.x;
    const int lane = tid & 31;
    const int w    = tid >> 5;
    const int g    = lane >> 2;
    const int t    = lane & 3;
    const int b    = blockIdx.y >> 4, h = blockIdx.y & 15;
    const int qb   = gridDim.x - 1 - blockIdx.x;   // heavy blocks first
    const int q0   = qb * FMr;
    const int causal = *mfp;
    const int nT   = causal ? 2 * (qb + 1) : (Sq / FNr);

    const float* Qbase = Qg + ((size_t)b * Sq + q0) * Dq + h * HDq;
    const float* Kbase = Kg + (size_t)b * Sq * Dq + h * HDq;
    const float* Vbase = Vg + (size_t)b * Sq * Dq + h * HDq;
    const int*   mbase = amask + b * Sq;

    const uint32_t Kraw_u = smem_u32(Kraw);
    const uint32_t Vraw_u = smem_u32(Vraw);

    auto prefetch = [&](int j, int s) {
        const float* Ksrc = Kbase + (size_t)(j * FNr) * Dq;
        const float* Vsrc = Vbase + (size_t)(j * FNr) * Dq;
        const uint32_t kd = Kraw_u + (uint32_t)(s * 64 * KRST) * 4;
        const uint32_t vd = Vraw_u + (uint32_t)(s * 64 * VRST) * 4;
#pragma unroll
        for (int i = 0; i < 4; i++) {
            const int e = i * 256 + tid;
            const int r = e >> 4, c4 = (e & 15) << 2;
            cp_async16(kd + (uint32_t)(r * KRST + c4) * 4, Ksrc + (size_t)r * Dq + c4);
            cp_async16(vd + (uint32_t)(r * VRST + c4) * 4, Vsrc + (size_t)r * Dq + c4);
        }
        if (tid < 64) msb[s * 64 + tid] = mbase[j * FNr + tid];
        cp_commit();
    };

    // ---- stage Q into Pb, build hi/lo Q fragments in registers ----
    prefetch(0, 0);
    for (int e = tid; e < FMr * 16; e += 256) {
        int r = e >> 4, c4 = (e & 15) << 2;
        *(float4*)&Pb[r * PST + c4] = *(const float4*)&Qbase[(size_t)r * Dq + c4];
    }
    __syncthreads();

    const int rA = w * 16 + g;
    uint32_t qhi[8][4], qlo[8][4];
#pragma unroll
    for (int kk = 0; kk < 8; kk++) {
        float v0 = Pb[rA * PST + kk * 8 + t];
        float v1 = Pb[(rA + 8) * PST + kk * 8 + t];
        float v2 = Pb[rA * PST + kk * 8 + t + 4];
        float v3 = Pb[(rA + 8) * PST + kk * 8 + t + 4];
        qhi[kk][0] = rtf32_bits(v0); qlo[kk][0] = rtf32_bits(v0 - __uint_as_float(qhi[kk][0]));
        qhi[kk][1] = rtf32_bits(v1); qlo[kk][1] = rtf32_bits(v1 - __uint_as_float(qhi[kk][1]));
        qhi[kk][2] = rtf32_bits(v2); qlo[kk][2] = rtf32_bits(v2 - __uint_as_float(qhi[kk][2]));
        qhi[kk][3] = rtf32_bits(v3); qlo[kk][3] = rtf32_bits(v3 - __uint_as_float(qhi[kk][3]));
    }

    float O[8][4];
#pragma unroll
    for (int nt = 0; nt < 8; nt++)
#pragma unroll
        for (int e = 0; e < 4; e++) O[nt][e] = 0.0f;
    float mAr = -1e30f, mBr = -1e30f, lAr = 0.0f, lBr = 0.0f;

    const int rgA = q0 + rA;
    const int rgB = rgA + 8;

    for (int j = 0; j < nT; j++) {
        const int s = j & 1;
        if (j + 1 < nT) { prefetch(j + 1, s ^ 1); cp_wait<1>(); }
        else            { cp_wait<0>(); }
        __syncthreads();                       // raw[s] visible; prior stage fully read

        // ---- convert pass: Kraw[s] -> Khl (hi,lo pairs), Vraw[s] -> Vr ----
        {
            const float* kr = Kraw + s * 64 * KRST;
            const float* vr = Vraw + s * 64 * VRST;
#pragma unroll
            for (int i = 0; i < 4; i++) {
                const int e = i * 256 + tid;
                const int r = e >> 4, c4 = (e & 15) << 2;
                float4 kv = *(const float4*)&kr[r * KRST + c4];
                const float kc[4] = {kv.x, kv.y, kv.z, kv.w};
#pragma unroll
                for (int e4 = 0; e4 < 4; e4++) {
                    const uint32_t hb = rtf32_bits(kc[e4]);
                    const uint32_t lb = rtf32_bits(kc[e4] - __uint_as_float(hb));
                    *(float2*)&Khl[r * KHLST + 2 * (c4 + e4)] =
                        make_float2(__uint_as_float(hb), __uint_as_float(lb));
                }
                float4 vv = *(const float4*)&vr[r * VRST + c4];
                vv.x = rtf32(vv.x); vv.y = rtf32(vv.y);
                vv.z = rtf32(vv.z); vv.w = rtf32(vv.w);
                *(float4*)&Vr[r * VRST + c4] = vv;
            }
        }
        __syncthreads();                       // Khl / Vr ready

        const int* ml = msb + s * 64;
        const int j0 = j * FNr;

        // ---- S = Q K^T (3xTF32, pure LDS+mma) ----
        float Sv[8][4];
#pragma unroll
        for (int nt = 0; nt < 8; nt++)
#pragma unroll
            for (int e = 0; e < 4; e++) Sv[nt][e] = 0.0f;

#pragma unroll
        for (int kk = 0; kk < 8; kk++) {
#pragma unroll
            for (int nt = 0; nt < 8; nt++) {
                const float2 h0 = *(const float2*)&Khl[(nt * 8 + g) * KHLST + 2 * (kk * 8 + t)];
                const float2 h1 = *(const float2*)&Khl[(nt * 8 + g) * KHLST + 2 * (kk * 8 + t + 4)];
                const uint32_t bh0 = __float_as_uint(h0.x);
                const uint32_t bl0 = __float_as_uint(h0.y);
                const uint32_t bh1 = __float_as_uint(h1.x);
                const uint32_t bl1 = __float_as_uint(h1.y);
                mma_tf32(Sv[nt][0], Sv[nt][1], Sv[nt][2], Sv[nt][3],
                         qhi[kk][0], qhi[kk][1], qhi[kk][2], qhi[kk][3], bl0, bl1);
                mma_tf32(Sv[nt][0], Sv[nt][1], Sv[nt][2], Sv[nt][3],
                         qlo[kk][0], qlo[kk][1], qlo[kk][2], qlo[kk][3], bh0, bh1);
                mma_tf32(Sv[nt][0], Sv[nt][1], Sv[nt][2], Sv[nt][3],
                         qhi[kk][0], qhi[kk][1], qhi[kk][2], qhi[kk][3], bh0, bh1);
            }
        }

        // ---- mask + scale + online softmax ----
        float rmA = -1e30f, rmB = -1e30f;
#pragma unroll
        for (int nt = 0; nt < 8; nt++) {
            const int2 mm = *(const int2*)&ml[nt * 8 + 2 * t];
            const int c0g = j0 + nt * 8 + 2 * t;
            const int c1g = c0g + 1;
            const bool d0 = (mm.x == 0), d1 = (mm.y == 0);
            Sv[nt][0] = (d0 || (causal && c0g > rgA)) ? -1e30f : Sv[nt][0] * 0.125f;
            Sv[nt][1] = (d1 || (causal && c1g > rgA)) ? -1e30f : Sv[nt][1] * 0.125f;
            Sv[nt][2] = (d0 || (causal && c0g > rgB)) ? -1e30f : Sv[nt][2] * 0.125f;
            Sv[nt][3] = (d1 || (causal && c1g > rgB)) ? -1e30f : Sv[nt][3] * 0.125f;
            rmA = fmaxf(rmA, fmaxf(Sv[nt][0], Sv[nt][1]));
            rmB = fmaxf(rmB, fmaxf(Sv[nt][2], Sv[nt][3]));
        }
        rmA = fmaxf(rmA, __shfl_xor_sync(0xffffffffu, rmA, 1));
        rmA = fmaxf(rmA, __shfl_xor_sync(0xffffffffu, rmA, 2));
        rmB = fmaxf(rmB, __shfl_xor_sync(0xffffffffu, rmB, 1));
        rmB = fmaxf(rmB, __shfl_xor_sync(0xffffffffu, rmB, 2));

        const float mnA = fmaxf(mAr, rmA);
        const float mnB = fmaxf(mBr, rmB);
        const float aA = __expf(mAr - mnA);
        const float aB = __expf(mBr - mnB);

        float sA = 0.0f, sB = 0.0f;
#pragma unroll
        for (int nt = 0; nt < 8; nt++) {
            float p0 = (Sv[nt][0] <= -1e29f) ? 0.0f : __expf(Sv[nt][0] - mnA);
            float p1 = (Sv[nt][1] <= -1e29f) ? 0.0f : __expf(Sv[nt][1] - mnA);
            float p2 = (Sv[nt][2] <= -1e29f) ? 0.0f : __expf(Sv[nt][2] - mnB);
            float p3 = (Sv[nt][3] <= -1e29f) ? 0.0f : __expf(Sv[nt][3] - mnB);
            sA += p0 + p1; sB += p2 + p3;
            // store pre-rounded P (tf32 bits) for the PV mma
            *(float2*)&Pb[rA * PST + nt * 8 + 2 * t] =
                make_float2(rtf32(p0), rtf32(p1));
            *(float2*)&Pb[(rA + 8) * PST + nt * 8 + 2 * t] =
                make_float2(rtf32(p2), rtf32(p3));
        }
        sA += __shfl_xor_sync(0xffffffffu, sA, 1);
        sA += __shfl_xor_sync(0xffffffffu, sA, 2);
        sB += __shfl_xor_sync(0xffffffffu, sB, 1);
        sB += __shfl_xor_sync(0xffffffffu, sB, 2);

        lAr = lAr * aA + sA; mAr = mnA;
        lBr = lBr * aB + sB; mBr = mnB;
#pragma unroll
        for (int nt = 0; nt < 8; nt++) {
            O[nt][0] *= aA; O[nt][1] *= aA;
            O[nt][2] *= aB; O[nt][3] *= aB;
        }
        __syncwarp();

        // ---- O += P V (pure LDS+mma; operands pre-rounded) ----
#pragma unroll
        for (int kk = 0; kk < 8; kk++) {
            const uint32_t a0 = __float_as_uint(Pb[rA * PST + kk * 8 + t]);
            const uint32_t a1 = __float_as_uint(Pb[(rA + 8) * PST + kk * 8 + t]);
            const uint32_t a2 = __float_as_uint(Pb[rA * PST + kk * 8 + t + 4]);
            const uint32_t a3 = __float_as_uint(Pb[(rA + 8) * PST + kk * 8 + t + 4]);
#pragma unroll
            for (int nt = 0; nt < 8; nt++) {
                const uint32_t b0 = __float_as_uint(Vr[(kk * 8 + t) * VRST + nt * 8 + g]);
                const uint32_t b1 = __float_as_uint(Vr[(kk * 8 + t + 4) * VRST + nt * 8 + g]);
                mma_tf32(O[nt][0], O[nt][1], O[nt][2], O[nt][3],
                         a0, a1, a2, a3, b0, b1);
            }
        }
        // next iteration's leading __syncthreads orders these reads
        // before the convert pass overwrites Khl/Vr
    }

    // ---- epilogue (store tf32-rounded: feeds tf32 output projection) ----
    const float iA = (lAr > 0.0f) ? (1.0f / lAr) : 0.0f;
    const float iB = (lBr > 0.0f) ? (1.0f / lBr) : 0.0f;
    float* CA = Ctx + ((size_t)b * Sq + rgA) * Dq + h * HDq;
    float* CB = Ctx + ((size_t)b * Sq + rgB) * Dq + h * HDq;
#pragma unroll
    for (int nt = 0; nt < 8; nt++) {
        *(float2*)&CA[nt * 8 + 2 * t] =
            make_float2(rtf32(O[nt][0] * iA), rtf32(O[nt][1] * iA));
        *(float2*)&CB[nt * 8 + 2 * t] =
            make_float2(rtf32(O[nt][2] * iB), rtf32(O[nt][3] * iB));
    }
}

// ---------------------------------------------------------------------------
// Exact cleanup for degenerate rows (all-padded causal prefix)
// ---------------------------------------------------------------------------
__global__ __launch_bounds__(256) void fix_degenerate(
    const float* __restrict__ Qg, const float* __restrict__ Kg,
    const float* __restrict__ Vg, const int* __restrict__ amask,
    const int* __restrict__ mfp, float* __restrict__ Ctx)
{
    const int b = blockIdx.x >> 4, h = blockIdx.x & 15;
    const int tid = threadIdx.x;
    const int causal = *mfp;

    __shared__ int   redi[256];
    __shared__ float redf[256];
    __shared__ float qrow[HDq];
    __shared__ float sc[Sq];

    int local = Sq;
    for (int s = tid; s < Sq; s += 256)
        if (amask[b * Sq + s]) local = min(local, s);
    redi[tid] = local;
    __syncthreads();
    for (int o = 128; o > 0; o >>= 1) {
        if (tid < o) redi[tid] = min(redi[tid], redi[tid + o]);
        __syncthreads();
    }
    const int s0 = redi[0];
    int nrows;
    if (causal) nrows = s0;
    else        nrows = (s0 == Sq) ? Sq : 0;
    if (nrows == 0) return;

    for (int i = 0; i < nrows; i++) {
        if (tid < HDq) qrow[tid] = Qg[((size_t)b * Sq + i) * Dq + h * HDq + tid];
        __syncthreads();

        for (int j = tid; j < Sq; j += 256) {
            const float* kr = Kg + ((size_t)b * Sq + j) * Dq + h * HDq;
            float acc = 0.0f;
#pragma unroll
            for (int d = 0; d < HDq; d++) acc = fmaf(qrow[d], kr[d], acc);
            float v = acc * 0.125f;
            if (causal && j > i) v += NEGB;
            if (amask[b * Sq + j] == 0) v = NEGB;
            sc[j] = v;
        }
        __syncthreads();

        float lm = -1e30f;
        for (int j = tid; j < Sq; j += 256) lm = fmaxf(lm, sc[j]);
        redf[tid] = lm; __syncthreads();
        for (int o = 128; o > 0; o >>= 1) {
            if (tid < o) redf[tid] = fmaxf(redf[tid], redf[tid + o]);
            __syncthreads();
        }
        const float m = redf[0];
        __syncthreads();

        float ls = 0.0f;
        for (int j = tid; j < Sq; j += 256) {
            float p = __expf(sc[j] - m);
            sc[j] = p;
            ls += p;
        }
        redf[tid] = ls; __syncthreads();
        for (int o = 128; o > 0; o >>= 1) {
            if (tid < o) redf[tid] += redf[tid + o];
            __syncthreads();
        }
        const float l = redf[0];
        __syncthreads();

        if (tid < HDq) {
            float acc = 0.0f;
            for (int j = 0; j < Sq; j++)
                acc = fmaf(sc[j], __ldg(&Vg[((size_t)b * Sq + j) * Dq + h * HDq + tid]), acc);
            Ctx[((size_t)b * Sq + i) * Dq + h * HDq + tid] = rtf32(acc / l);
        }
        __syncthreads();
    }
}

// ---------------------------------------------------------------------------
// Launch
// ---------------------------------------------------------------------------
extern "C" void kernel_launch(void* const* d_in, const int* in_sizes, int n_in,
                              void* d_out, int out_size)
{
    const float* q     = (const float*)d_in[0];
    const float* k     = (const float*)d_in[1];
    const float* v     = (const float*)d_in[2];
    const int*   amask = (const int*)  d_in[3];
    const float* Wq    = (const float*)d_in[4];
    const float* Wk    = (const float*)d_in[5];
    const float* Wv    = (const float*)d_in[6];
    const float* Wo    = (const float*)d_in[7];
    const int*   mf    = (const int*)  d_in[8];
    float*       out   = (float*)d_out;

    float *gQ, *gK, *gV, *gC, *gA, *gW;
    cudaGetSymbolAddress((void**)&gQ, g_Q);
    cudaGetSymbolAddress((void**)&gK, g_K);
    cudaGetSymbolAddress((void**)&gV, g_V);
    cudaGetSymbolAddress((void**)&gC, g_C);
    cudaGetSymbolAddress((void**)&gA, g_A);
    cudaGetSymbolAddress((void**)&gW, g_W);

    cudaFuncSetAttribute(gemm_tf32, cudaFuncAttributeMaxDynamicSharedMemorySize,
                         (int)GEMM_SMEM);
    cudaFuncSetAttribute(flash_mma, cudaFuncAttributeMaxDynamicSharedMemorySize,
                         (int)FL_SMEM);

    const int n4a = Bq * Sq * Dq / 4;
    const int n4w = Dq * Dq / 4;
    const int M = Bq * Sq;                    // 4096
    const dim3 gg(Dq / 128, M / 128);         // (8, 32)

    // Q projection
    round_tf32_kernel<<<(n4a + 255) / 256, 256>>>(q, gA, n4a);
    round_tf32_kernel<<<(n4w + 255) / 256, 256>>>(Wq, gW, n4w);
    gemm_tf32<<<gg, 256, GEMM_SMEM>>>(gA, gW, gQ);
    // K projection
    round_tf32_kernel<<<(n4a + 255) / 256, 256>>>(k, gA, n4a);
    round_tf32_kernel<<<(n4w + 255) / 256, 256>>>(Wk, gW, n4w);
    gemm_tf32<<<gg, 256, GEMM_SMEM>>>(gA, gW, gK);
    // V projection
    round_tf32_kernel<<<(n4a + 255) / 256, 256>>>(v, gA, n4a);
    round_tf32_kernel<<<(n4w + 255) / 256, 256>>>(Wv, gW, n4w);
    gemm_tf32<<<gg, 256, GEMM_SMEM>>>(gA, gW, gV);

    // Attention (ctx stored tf32-rounded)
    flash_mma<<<dim3(Sq / FMr, Bq * Hq), 256, FL_SMEM>>>(gQ, gK, gV, amask, mf, gC);
    fix_degenerate<<<Bq * Hq, 256>>>(gQ, gK, gV, amask, mf, gC);

    // Output projection
    round_tf32_kernel<<<(n4w + 255) / 256, 256>>>(Wo, gW, n4w);
    gemm_tf32<<<gg, 256, GEMM_SMEM>>>(gC, gW, out);
}

// round 7
// speedup vs baseline: 2.5705x; 1.0727x over previous
#include <cuda_runtime.h>
#include <math.h>
#include <stdint.h>

// Problem constants
constexpr int Bq  = 2;
constexpr int Sq  = 2048;
constexpr int Dq  = 1024;
constexpr int Hq  = 16;
constexpr int HDq = 64;
constexpr float NEGB = -10000.0f;

// ---------------------------------------------------------------------------
// Scratch (device globals: no allocation allowed)
// ---------------------------------------------------------------------------
__device__ __align__(16) float g_Q[Bq * Sq * Dq];
__device__ __align__(16) float g_K[Bq * Sq * Dq];
__device__ __align__(16) float g_V[Bq * Sq * Dq];
__device__ __align__(16) float g_C[Bq * Sq * Dq];
__device__ __align__(16) float g_A1[Bq * Sq * Dq];  // rounded q
__device__ __align__(16) float g_A2[Bq * Sq * Dq];  // rounded k
__device__ __align__(16) float g_A3[Bq * Sq * Dq];  // rounded v
__device__ __align__(16) float g_W1[Dq * Dq];       // rounded Wq
__device__ __align__(16) float g_W2[Dq * Dq];       // rounded Wk
__device__ __align__(16) float g_W3[Dq * Dq];       // rounded Wv
__device__ __align__(16) float g_W4[Dq * Dq];       // rounded Wo

// ---------------------------------------------------------------------------
// Helpers
// ---------------------------------------------------------------------------
__device__ __forceinline__ uint32_t rtf32_bits(float x) {
    uint32_t u;
    asm("cvt.rna.tf32.f32 %0, %1;" : "=r"(u) : "f"(x));
    return u;
}
__device__ __forceinline__ float rtf32(float x) {
    return __uint_as_float(rtf32_bits(x));
}

__global__ __launch_bounds__(256) void round_qkv_kernel(
    const float* __restrict__ a, const float* __restrict__ b,
    const float* __restrict__ c,
    float* __restrict__ oa, float* __restrict__ ob, float* __restrict__ oc)
{
    const int i = blockIdx.x * blockDim.x + threadIdx.x;
    const float* src = (blockIdx.z == 0) ? a : (blockIdx.z == 1) ? b : c;
    float* dst = (blockIdx.z == 0) ? oa : (blockIdx.z == 1) ? ob : oc;
    float4 v = ((const float4*)src)[i];
    float4 o;
    o.x = rtf32(v.x); o.y = rtf32(v.y); o.z = rtf32(v.z); o.w = rtf32(v.w);
    ((float4*)dst)[i] = o;
}

__global__ __launch_bounds__(256) void round_w_kernel(
    const float* __restrict__ a, const float* __restrict__ b,
    const float* __restrict__ c, const float* __restrict__ d,
    float* __restrict__ oa, float* __restrict__ ob,
    float* __restrict__ oc, float* __restrict__ od)
{
    const int i = blockIdx.x * blockDim.x + threadIdx.x;
    const float* src = (blockIdx.z == 0) ? a : (blockIdx.z == 1) ? b
                     : (blockIdx.z == 2) ? c : d;
    float* dst = (blockIdx.z == 0) ? oa : (blockIdx.z == 1) ? ob
               : (blockIdx.z == 2) ? oc : od;
    float4 v = ((const float4*)src)[i];
    float4 o;
    o.x = rtf32(v.x); o.y = rtf32(v.y); o.z = rtf32(v.z); o.w = rtf32(v.w);
    ((float4*)dst)[i] = o;
}

__device__ __forceinline__ void mma_tf32(
    float& c0, float& c1, float& c2, float& c3,
    uint32_t a0, uint32_t a1, uint32_t a2, uint32_t a3,
    uint32_t b0, uint32_t b1)
{
    asm volatile(
        "mma.sync.aligned.m16n8k8.row.col.f32.tf32.tf32.f32 "
        "{%0,%1,%2,%3}, {%4,%5,%6,%7}, {%8,%9}, {%0,%1,%2,%3};"
        : "+f"(c0), "+f"(c1), "+f"(c2), "+f"(c3)
        : "r"(a0), "r"(a1), "r"(a2), "r"(a3), "r"(b0), "r"(b1));
}

__device__ __forceinline__ uint32_t smem_u32(const void* p) {
    uint32_t a;
    asm("{ .reg .u64 t; cvta.to.shared.u64 t, %1; cvt.u32.u64 %0, t; }"
        : "=r"(a) : "l"(p));
    return a;
}

__device__ __forceinline__ void cp_async16(uint32_t dst, const void* src) {
    asm volatile("cp.async.cg.shared.global [%0], [%1], 16;"
                 :: "r"(dst), "l"(src) : "memory");
}
__device__ __forceinline__ void cp_commit() {
    asm volatile("cp.async.commit_group;" ::: "memory");
}
template <int N>
__device__ __forceinline__ void cp_wait() {
    asm volatile("cp.async.wait_group %0;" :: "n"(N) : "memory");
}

// ---------------------------------------------------------------------------
// tf32 mma.sync GEMM body: C[M,N] = A[M,K] @ W[N,K]^T, fp32 accumulate.
// Inputs pre-rounded to tf32. CTA 128x128, BK=32, 3-stage cp.async pipeline.
// 2 CTAs/SM (221 KB smem pair, regs capped at 128 via launch bounds).
// ---------------------------------------------------------------------------
constexpr int GP   = 36;                      // smem row stride (floats)
constexpr int STGF = 128 * GP;                // floats per operand-stage
constexpr int NSTG = 3;
constexpr uint32_t GEMM_SMEM = NSTG * 2 * STGF * 4;  // 110592 B

__device__ __forceinline__ void gemm_body(
    const float* __restrict__ A, const float* __restrict__ Wt,
    float* __restrict__ C, float* sm)
{
    const int tid  = threadIdx.x;
    const int lane = tid & 31;
    const int wid  = tid >> 5;
    const int g    = lane >> 2;
    const int t    = lane & 3;
    const int wm0  = (wid & 1) * 64;
    const int wn0  = (wid >> 1) * 32;
    const int m0   = blockIdx.y * 128;
    const int n0   = blockIdx.x * 128;
    const uint32_t sm_u = smem_u32(sm);

    auto prefetch = [&](int c, int s) {
        const int kc = c * 32;
        const uint32_t as = sm_u + (uint32_t)(s * 2 * STGF) * 4;
        const uint32_t bs = as + (uint32_t)STGF * 4;
#pragma unroll
        for (int i = 0; i < 4; i++) {
            const int id = i * 256 + tid;
            const int rr = id >> 3;
            const int c4 = (id & 7) * 4;
            cp_async16(as + (uint32_t)(rr * GP + c4) * 4,
                       A + (size_t)(m0 + rr) * Dq + kc + c4);
            cp_async16(bs + (uint32_t)(rr * GP + c4) * 4,
                       Wt + (size_t)(n0 + rr) * Dq + kc + c4);
        }
        cp_commit();
    };

    float cr[4][4][4];
#pragma unroll
    for (int i = 0; i < 4; i++)
#pragma unroll
        for (int j = 0; j < 4; j++)
#pragma unroll
            for (int e = 0; e < 4; e++) cr[i][j][e] = 0.0f;

    prefetch(0, 0);
    prefetch(1, 1);

    constexpr int NCH = Dq / 32;   // 32
    for (int c = 0; c < NCH; c++) {
        if (c == NCH - 1) cp_wait<0>(); else cp_wait<1>();
        __syncthreads();
        if (c + 2 < NCH) prefetch(c + 2, (c + 2) % NSTG);

        const float* As = sm + (c % NSTG) * 2 * STGF;
        const float* Bs = As + STGF;
#pragma unroll
        for (int kk = 0; kk < 32; kk += 8) {
            uint32_t af[4][4], bf[4][2];
#pragma unroll
            for (int mt = 0; mt < 4; mt++) {
                const int row = wm0 + mt * 16 + g;
                af[mt][0] = __float_as_uint(As[row * GP + kk + t]);
                af[mt][1] = __float_as_uint(As[(row + 8) * GP + kk + t]);
                af[mt][2] = __float_as_uint(As[row * GP + kk + t + 4]);
                af[mt][3] = __float_as_uint(As[(row + 8) * GP + kk + t + 4]);
            }
#pragma unroll
            for (int nt = 0; nt < 4; nt++) {
                const int row = wn0 + nt * 8 + g;
                bf[nt][0] = __float_as_uint(Bs[row * GP + kk + t]);
                bf[nt][1] = __float_as_uint(Bs[row * GP + kk + t + 4]);
            }
#pragma unroll
            for (int mt = 0; mt < 4; mt++)
#pragma unroll
                for (int nt = 0; nt < 4; nt++)
                    mma_tf32(cr[mt][nt][0], cr[mt][nt][1],
                             cr[mt][nt][2], cr[mt][nt][3],
                             af[mt][0], af[mt][1], af[mt][2], af[mt][3],
                             bf[nt][0], bf[nt][1]);
        }
    }

#pragma unroll
    for (int mt = 0; mt < 4; mt++) {
#pragma unroll
        for (int nt = 0; nt < 4; nt++) {
            const int row = m0 + wm0 + mt * 16 + g;
            const int col = n0 + wn0 + nt * 8 + 2 * t;
            *(float2*)&C[(size_t)row * Dq + col] =
                make_float2(cr[mt][nt][0], cr[mt][nt][1]);
            *(float2*)&C[(size_t)(row + 8) * Dq + col] =
                make_float2(cr[mt][nt][2], cr[mt][nt][3]);
        }
    }
}

__global__ __launch_bounds__(256, 2) void gemm_tf32(
    const float* __restrict__ A, const float* __restrict__ Wt,
    float* __restrict__ C)
{
    extern __shared__ __align__(16) float sm[];
    gemm_body(A, Wt, C, sm);
}

__global__ __launch_bounds__(256, 2) void gemm_tf32_b3(
    const float* __restrict__ A0, const float* __restrict__ A1,
    const float* __restrict__ A2,
    const float* __restrict__ W0, const float* __restrict__ W1,
    const float* __restrict__ W2,
    float* __restrict__ C0, float* __restrict__ C1, float* __restrict__ C2)
{
    extern __shared__ __align__(16) float sm[];
    const float* A = (blockIdx.z == 0) ? A0 : (blockIdx.z == 1) ? A1 : A2;
    const float* W = (blockIdx.z == 0) ? W0 : (blockIdx.z == 1) ? W1 : W2;
    float*       C = (blockIdx.z == 0) ? C0 : (blockIdx.z == 1) ? C1 : C2;
    gemm_body(A, W, C, sm);
}

// ---------------------------------------------------------------------------
// Tensor-core flash attention, hoisted conversions, 2-mma split scores.
// S = qhi*(khi+klo): Q single-rounded (rna), K hi/lo split. Error added vs
// fp32 scores ~2.8e-4 in quadrature (calibrated on round-4 PV delta).
// ---------------------------------------------------------------------------
constexpr int FMr = 128, FNr = 64;
constexpr int KRST = 68, VRST = 72, KHLST = 136, PST = 68;
constexpr int OFF_KRAW = 0;                         // [2][64*68]
constexpr int OFF_VRAW = OFF_KRAW + 2 * 64 * KRST;  // [2][64*72]
constexpr int OFF_KHL  = OFF_VRAW + 2 * 64 * VRST;  // [64*136]
constexpr int OFF_VR   = OFF_KHL + 64 * KHLST;      // [64*72]
constexpr int OFF_PB   = OFF_VR + 64 * VRST;        // [128*68]
constexpr int FL_FLOATS = OFF_PB + FMr * PST;
constexpr uint32_t FL_SMEM = FL_FLOATS * 4 + 2 * 64 * 4;

__global__ __launch_bounds__(256, 1) void flash_mma(
    const float* __restrict__ Qg, const float* __restrict__ Kg,
    const float* __restrict__ Vg, const int* __restrict__ amask,
    const int* __restrict__ mfp, float* __restrict__ Ctx)
{
    extern __shared__ __align__(16) float fs[];
    float* Kraw = fs + OFF_KRAW;
    float* Vraw = fs + OFF_VRAW;
    float* Khl  = fs + OFF_KHL;
    float* Vr   = fs + OFF_VR;
    float* Pb   = fs + OFF_PB;
    int*   msb  = (int*)(fs + FL_FLOATS);

    const int tid  = threadIdx.x;
    const int lane = tid & 31;
    const int w    = tid >> 5;
    const int g    = lane >> 2;
    const int t    = lane & 3;
    const int b    = blockIdx.y >> 4, h = blockIdx.y & 15;
    const int qb   = gridDim.x - 1 - blockIdx.x;   // heavy blocks first
    const int q0   = qb * FMr;
    const int causal = *mfp;
    const int nT   = causal ? 2 * (qb + 1) : (Sq / FNr);

    const float* Qbase = Qg + ((size_t)b * Sq + q0) * Dq + h * HDq;
    const float* Kbase = Kg + (size_t)b * Sq * Dq + h * HDq;
    const float* Vbase = Vg + (size_t)b * Sq * Dq + h * HDq;
    const int*   mbase = amask + b * Sq;

    const uint32_t Kraw_u = smem_u32(Kraw);
    const uint32_t Vraw_u = smem_u32(Vraw);

    auto prefetch = [&](int j, int s) {
        const float* Ksrc = Kbase + (size_t)(j * FNr) * Dq;
        const float* Vsrc = Vbase + (size_t)(j * FNr) * Dq;
        const uint32_t kd = Kraw_u + (uint32_t)(s * 64 * KRST) * 4;
        const uint32_t vd = Vraw_u + (uint32_t)(s * 64 * VRST) * 4;
#pragma unroll
        for (int i = 0; i < 4; i++) {
            const int e = i * 256 + tid;
            const int r = e >> 4, c4 = (e & 15) << 2;
            cp_async16(kd + (uint32_t)(r * KRST + c4) * 4, Ksrc + (size_t)r * Dq + c4);
            cp_async16(vd + (uint32_t)(r * VRST + c4) * 4, Vsrc + (size_t)r * Dq + c4);
        }
        if (tid < 64) msb[s * 64 + tid] = mbase[j * FNr + tid];
        cp_commit();
    };

    // ---- stage Q into Pb, build single-rounded Q fragments ----
    prefetch(0, 0);
    for (int e = tid; e < FMr * 16; e += 256) {
        int r = e >> 4, c4 = (e & 15) << 2;
        *(float4*)&Pb[r * PST + c4] = *(const float4*)&Qbase[(size_t)r * Dq + c4];
    }
    __syncthreads();

    const int rA = w * 16 + g;
    uint32_t qhi[8][4];
#pragma unroll
    for (int kk = 0; kk < 8; kk++) {
        qhi[kk][0] = rtf32_bits(Pb[rA * PST + kk * 8 + t]);
        qhi[kk][1] = rtf32_bits(Pb[(rA + 8) * PST + kk * 8 + t]);
        qhi[kk][2] = rtf32_bits(Pb[rA * PST + kk * 8 + t + 4]);
        qhi[kk][3] = rtf32_bits(Pb[(rA + 8) * PST + kk * 8 + t + 4]);
    }

    float O[8][4];
#pragma unroll
    for (int nt = 0; nt < 8; nt++)
#pragma unroll
        for (int e = 0; e < 4; e++) O[nt][e] = 0.0f;
    float mAr = -1e30f, mBr = -1e30f, lAr = 0.0f, lBr = 0.0f;

    const int rgA = q0 + rA;
    const int rgB = rgA + 8;

    for (int j = 0; j < nT; j++) {
        const int s = j & 1;
        if (j + 1 < nT) { prefetch(j + 1, s ^ 1); cp_wait<1>(); }
        else            { cp_wait<0>(); }
        __syncthreads();                       // raw[s] visible; prior stage fully read

        // ---- convert pass: Kraw[s] -> Khl (hi,lo pairs), Vraw[s] -> Vr ----
        {
            const float* kr = Kraw + s * 64 * KRST;
            const float* vr = Vraw + s * 64 * VRST;
#pragma unroll
            for (int i = 0; i < 4; i++) {
                const int e = i * 256 + tid;
                const int r = e >> 4, c4 = (e & 15) << 2;
                float4 kv = *(const float4*)&kr[r * KRST + c4];
                const float kc[4] = {kv.x, kv.y, kv.z, kv.w};
#pragma unroll
                for (int e4 = 0; e4 < 4; e4++) {
                    const uint32_t hb = rtf32_bits(kc[e4]);
                    const uint32_t lb = rtf32_bits(kc[e4] - __uint_as_float(hb));
                    *(float2*)&Khl[r * KHLST + 2 * (c4 + e4)] =
                        make_float2(__uint_as_float(hb), __uint_as_float(lb));
                }
                float4 vv = *(const float4*)&vr[r * VRST + c4];
                vv.x = rtf32(vv.x); vv.y = rtf32(vv.y);
                vv.z = rtf32(vv.z); vv.w = rtf32(vv.w);
                *(float4*)&Vr[r * VRST + c4] = vv;
            }
        }
        __syncthreads();                       // Khl / Vr ready

        const int* ml = msb + s * 64;
        const int j0 = j * FNr;

        // ---- S = qhi*(khi+klo)  (2 mmas per fragment pair) ----
        float Sv[8][4];
#pragma unroll
        for (int nt = 0; nt < 8; nt++)
#pragma unroll
            for (int e = 0; e < 4; e++) Sv[nt][e] = 0.0f;

#pragma unroll
        for (int kk = 0; kk < 8; kk++) {
#pragma unroll
            for (int nt = 0; nt < 8; nt++) {
                const float2 h0 = *(const float2*)&Khl[(nt * 8 + g) * KHLST + 2 * (kk * 8 + t)];
                const float2 h1 = *(const float2*)&Khl[(nt * 8 + g) * KHLST + 2 * (kk * 8 + t + 4)];
                const uint32_t bh0 = __float_as_uint(h0.x);
                const uint32_t bl0 = __float_as_uint(h0.y);
                const uint32_t bh1 = __float_as_uint(h1.x);
                const uint32_t bl1 = __float_as_uint(h1.y);
                mma_tf32(Sv[nt][0], Sv[nt][1], Sv[nt][2], Sv[nt][3],
                         qhi[kk][0], qhi[kk][1], qhi[kk][2], qhi[kk][3], bl0, bl1);
                mma_tf32(Sv[nt][0], Sv[nt][1], Sv[nt][2], Sv[nt][3],
                         qhi[kk][0], qhi[kk][1], qhi[kk][2], qhi[kk][3], bh0, bh1);
            }
        }

        // ---- mask + scale + online softmax ----
        float rmA = -1e30f, rmB = -1e30f;
#pragma unroll
        for (int nt = 0; nt < 8; nt++) {
            const int2 mm = *(const int2*)&ml[nt * 8 + 2 * t];
            const int c0g = j0 + nt * 8 + 2 * t;
            const int c1g = c0g + 1;
            const bool d0 = (mm.x == 0), d1 = (mm.y == 0);
            Sv[nt][0] = (d0 || (causal && c0g > rgA)) ? -1e30f : Sv[nt][0] * 0.125f;
            Sv[nt][1] = (d1 || (causal && c1g > rgA)) ? -1e30f : Sv[nt][1] * 0.125f;
            Sv[nt][2] = (d0 || (causal && c0g > rgB)) ? -1e30f : Sv[nt][2] * 0.125f;
            Sv[nt][3] = (d1 || (causal && c1g > rgB)) ? -1e30f : Sv[nt][3] * 0.125f;
            rmA = fmaxf(rmA, fmaxf(Sv[nt][0], Sv[nt][1]));
            rmB = fmaxf(rmB, fmaxf(Sv[nt][2], Sv[nt][3]));
        }
        rmA = fmaxf(rmA, __shfl_xor_sync(0xffffffffu, rmA, 1));
        rmA = fmaxf(rmA, __shfl_xor_sync(0xffffffffu, rmA, 2));
        rmB = fmaxf(rmB, __shfl_xor_sync(0xffffffffu, rmB, 1));
        rmB = fmaxf(rmB, __shfl_xor_sync(0xffffffffu, rmB, 2));

        const float mnA = fmaxf(mAr, rmA);
        const float mnB = fmaxf(mBr, rmB);
        const float aA = __expf(mAr - mnA);
        const float aB = __expf(mBr - mnB);

        float sA = 0.0f, sB = 0.0f;
#pragma unroll
        for (int nt = 0; nt < 8; nt++) {
            float p0 = (Sv[nt][0] <= -1e29f) ? 0.0f : __expf(Sv[nt][0] - mnA);
            float p1 = (Sv[nt][1] <= -1e29f) ? 0.0f : __expf(Sv[nt][1] - mnA);
            float p2 = (Sv[nt][2] <= -1e29f) ? 0.0f : __expf(Sv[nt][2] - mnB);
            float p3 = (Sv[nt][3] <= -1e29f) ? 0.0f : __expf(Sv[nt][3] - mnB);
            sA += p0 + p1; sB += p2 + p3;
            *(float2*)&Pb[rA * PST + nt * 8 + 2 * t] =
                make_float2(rtf32(p0), rtf32(p1));
            *(float2*)&Pb[(rA + 8) * PST + nt * 8 + 2 * t] =
                make_float2(rtf32(p2), rtf32(p3));
        }
        sA += __shfl_xor_sync(0xffffffffu, sA, 1);
        sA += __shfl_xor_sync(0xffffffffu, sA, 2);
        sB += __shfl_xor_sync(0xffffffffu, sB, 1);
        sB += __shfl_xor_sync(0xffffffffu, sB, 2);

        lAr = lAr * aA + sA; mAr = mnA;
        lBr = lBr * aB + sB; mBr = mnB;
#pragma unroll
        for (int nt = 0; nt < 8; nt++) {
            O[nt][0] *= aA; O[nt][1] *= aA;
            O[nt][2] *= aB; O[nt][3] *= aB;
        }
        __syncwarp();

        // ---- O += P V (pure LDS+mma; operands pre-rounded) ----
#pragma unroll
        for (int kk = 0; kk < 8; kk++) {
            const uint32_t a0 = __float_as_uint(Pb[rA * PST + kk * 8 + t]);
            const uint32_t a1 = __float_as_uint(Pb[(rA + 8) * PST + kk * 8 + t]);
            const uint32_t a2 = __float_as_uint(Pb[rA * PST + kk * 8 + t + 4]);
            const uint32_t a3 = __float_as_uint(Pb[(rA + 8) * PST + kk * 8 + t + 4]);
#pragma unroll
            for (int nt = 0; nt < 8; nt++) {
                const uint32_t b0 = __float_as_uint(Vr[(kk * 8 + t) * VRST + nt * 8 + g]);
                const uint32_t b1 = __float_as_uint(Vr[(kk * 8 + t + 4) * VRST + nt * 8 + g]);
                mma_tf32(O[nt][0], O[nt][1], O[nt][2], O[nt][3],
                         a0, a1, a2, a3, b0, b1);
            }
        }
    }

    // ---- epilogue (store tf32-rounded: feeds tf32 output projection) ----
    const float iA = (lAr > 0.0f) ? (1.0f / lAr) : 0.0f;
    const float iB = (lBr > 0.0f) ? (1.0f / lBr) : 0.0f;
    float* CA = Ctx + ((size_t)b * Sq + rgA) * Dq + h * HDq;
    float* CB = Ctx + ((size_t)b * Sq + rgB) * Dq + h * HDq;
#pragma unroll
    for (int nt = 0; nt < 8; nt++) {
        *(float2*)&CA[nt * 8 + 2 * t] =
            make_float2(rtf32(O[nt][0] * iA), rtf32(O[nt][1] * iA));
        *(float2*)&CB[nt * 8 + 2 * t] =
            make_float2(rtf32(O[nt][2] * iB), rtf32(O[nt][3] * iB));
    }
}

// ---------------------------------------------------------------------------
// Exact cleanup for degenerate rows (all-padded causal prefix)
// ---------------------------------------------------------------------------
__global__ __launch_bounds__(256) void fix_degenerate(
    const float* __restrict__ Qg, const float* __restrict__ Kg,
    const float* __restrict__ Vg, const int* __restrict__ amask,
    const int* __restrict__ mfp, float* __restrict__ Ctx)
{
    const int b = blockIdx.x >> 4, h = blockIdx.x & 15;
    const int tid = threadIdx.x;
    const int causal = *mfp;

    __shared__ int   redi[256];
    __shared__ float redf[256];
    __shared__ float qrow[HDq];
    __shared__ float sc[Sq];

    int local = Sq;
    for (int s = tid; s < Sq; s += 256)
        if (amask[b * Sq + s]) local = min(local, s);
    redi[tid] = local;
    __syncthreads();
    for (int o = 128; o > 0; o >>= 1) {
        if (tid < o) redi[tid] = min(redi[tid], redi[tid + o]);
        __syncthreads();
    }
    const int s0 = redi[0];
    int nrows;
    if (causal) nrows = s0;
    else        nrows = (s0 == Sq) ? Sq : 0;
    if (nrows == 0) return;

    for (int i = 0; i < nrows; i++) {
        if (tid < HDq) qrow[tid] = Qg[((size_t)b * Sq + i) * Dq + h * HDq + tid];
        __syncthreads();

        for (int j = tid; j < Sq; j += 256) {
            const float* kr = Kg + ((size_t)b * Sq + j) * Dq + h * HDq;
            float acc = 0.0f;
#pragma unroll
            for (int d = 0; d < HDq; d++) acc = fmaf(qrow[d], kr[d], acc);
            float v = acc * 0.125f;
            if (causal && j > i) v += NEGB;
            if (amask[b * Sq + j] == 0) v = NEGB;
            sc[j] = v;
        }
        __syncthreads();

        float lm = -1e30f;
        for (int j = tid; j < Sq; j += 256) lm = fmaxf(lm, sc[j]);
        redf[tid] = lm; __syncthreads();
        for (int o = 128; o > 0; o >>= 1) {
            if (tid < o) redf[tid] = fmaxf(redf[tid], redf[tid + o]);
            __syncthreads();
        }
        const float m = redf[0];
        __syncthreads();

        float ls = 0.0f;
        for (int j = tid; j < Sq; j += 256) {
            float p = __expf(sc[j] - m);
            sc[j] = p;
            ls += p;
        }
        redf[tid] = ls; __syncthreads();
        for (int o = 128; o > 0; o >>= 1) {
            if (tid < o) redf[tid] += redf[tid + o];
            __syncthreads();
        }
        const float l = redf[0];
        __syncthreads();

        if (tid < HDq) {
            float acc = 0.0f;
            for (int j = 0; j < Sq; j++)
                acc = fmaf(sc[j], __ldg(&Vg[((size_t)b * Sq + j) * Dq + h * HDq + tid]), acc);
            Ctx[((size_t)b * Sq + i) * Dq + h * HDq + tid] = rtf32(acc / l);
        }
        __syncthreads();
    }
}

// ---------------------------------------------------------------------------
// Launch
// ---------------------------------------------------------------------------
extern "C" void kernel_launch(void* const* d_in, const int* in_sizes, int n_in,
                              void* d_out, int out_size)
{
    const float* q     = (const float*)d_in[0];
    const float* k     = (const float*)d_in[1];
    const float* v     = (const float*)d_in[2];
    const int*   amask = (const int*)  d_in[3];
    const float* Wq    = (const float*)d_in[4];
    const float* Wk    = (const float*)d_in[5];
    const float* Wv    = (const float*)d_in[6];
    const float* Wo    = (const float*)d_in[7];
    const int*   mf    = (const int*)  d_in[8];
    float*       out   = (float*)d_out;

    float *gQ, *gK, *gV, *gC, *gA1, *gA2, *gA3, *gW1, *gW2, *gW3, *gW4;
    cudaGetSymbolAddress((void**)&gQ, g_Q);
    cudaGetSymbolAddress((void**)&gK, g_K);
    cudaGetSymbolAddress((void**)&gV, g_V);
    cudaGetSymbolAddress((void**)&gC, g_C);
    cudaGetSymbolAddress((void**)&gA1, g_A1);
    cudaGetSymbolAddress((void**)&gA2, g_A2);
    cudaGetSymbolAddress((void**)&gA3, g_A3);
    cudaGetSymbolAddress((void**)&gW1, g_W1);
    cudaGetSymbolAddress((void**)&gW2, g_W2);
    cudaGetSymbolAddress((void**)&gW3, g_W3);
    cudaGetSymbolAddress((void**)&gW4, g_W4);

    cudaFuncSetAttribute(gemm_tf32, cudaFuncAttributeMaxDynamicSharedMemorySize,
                         (int)GEMM_SMEM);
    cudaFuncSetAttribute(gemm_tf32_b3, cudaFuncAttributeMaxDynamicSharedMemorySize,
                         (int)GEMM_SMEM);
    cudaFuncSetAttribute(flash_mma, cudaFuncAttributeMaxDynamicSharedMemorySize,
                         (int)FL_SMEM);

    const int n4a = Bq * Sq * Dq / 4;         // 1,048,576
    const int n4w = Dq * Dq / 4;              // 262,144
    const int M = Bq * Sq;                    // 4096

    // Round all operands (2 launches)
    round_qkv_kernel<<<dim3(n4a / 256, 1, 3), 256>>>(q, k, v, gA1, gA2, gA3);
    round_w_kernel<<<dim3(n4w / 256, 1, 4), 256>>>(Wq, Wk, Wv, Wo,
                                                   gW1, gW2, gW3, gW4);

    // Fused QKV projections (one launch, z selects operand set)
    gemm_tf32_b3<<<dim3(Dq / 128, M / 128, 3), 256, GEMM_SMEM>>>(
        gA1, gA2, gA3, gW1, gW2, gW3, gQ, gK, gV);

    // Attention (ctx stored tf32-rounded)
    flash_mma<<<dim3(Sq / FMr, Bq * Hq), 256, FL_SMEM>>>(gQ, gK, gV, amask, mf, gC);
    fix_degenerate<<<Bq * Hq, 256>>>(gQ, gK, gV, amask, mf, gC);

    // Output projection
    gemm_tf32<<<dim3(Dq / 128, M / 128), 256, GEMM_SMEM>>>(gC, gW4, out);
}